// round 12
// baseline (speedup 1.0000x reference)
#include <cuda_runtime.h>
#include <cuda_bf16.h>
#include <cstdint>
#include <math.h>

#define INST   64
#define NVOCAB 128
#define ED     256
#define HID    1024
#define BATCH  2048

// Precomputed HL[i] = E_l[i] @ W1[i], HR[i] = E_r[i] @ W1[i]  (fp32 scratch)
__device__ float g_HL[INST * NVOCAB * HID];
__device__ float g_HR[INST * NVOCAB * HID];
// W2 transposed + tf32: [inst][n][k]  (filled by phase1 tail)
__device__ uint32_t g_W2t[INST * NVOCAB * HID];

__device__ __forceinline__ uint32_t f2tf(float f) {
    uint32_t u;
    asm("cvt.rna.tf32.f32 %0, %1;" : "=r"(u) : "f"(f));
    return u;
}
__device__ __forceinline__ void mma8(float* c, const uint32_t* a, const uint32_t* b) {
    asm volatile(
        "mma.sync.aligned.m16n8k8.row.col.f32.tf32.tf32.f32 "
        "{%0,%1,%2,%3}, {%4,%5,%6,%7}, {%8,%9}, {%0,%1,%2,%3};"
        : "+f"(c[0]), "+f"(c[1]), "+f"(c[2]), "+f"(c[3])
        : "r"(a[0]), "r"(a[1]), "r"(a[2]), "r"(a[3]), "r"(b[0]), "r"(b[1]));
}
__device__ __forceinline__ void ldsm4(uint32_t& r0, uint32_t& r1, uint32_t& r2,
                                      uint32_t& r3, uint32_t addr) {
    asm volatile("ldmatrix.sync.aligned.m8n8.x4.shared.b16 {%0,%1,%2,%3}, [%4];"
                 : "=r"(r0), "=r"(r1), "=r"(r2), "=r"(r3) : "r"(addr));
}
__device__ __forceinline__ uint32_t smem_u32(const void* p) {
    uint32_t a;
    asm("{ .reg .u64 t; cvta.to.shared.u64 t, %1; cvt.u32.u64 %0, t; }" : "=r"(a) : "l"(p));
    return a;
}
#define MBAR_INIT(addr, cnt) \
    asm volatile("mbarrier.init.shared.b64 [%0], %1;" :: "r"(addr), "r"(cnt) : "memory")
#define MBAR_ARRIVE(addr) \
    asm volatile("mbarrier.arrive.release.cta.shared::cta.b64 _, [%0];" :: "r"(addr) : "memory")
__device__ __forceinline__ void mbar_wait(uint32_t addr, uint32_t parity) {
    asm volatile(
        "{ .reg .pred P;\n"
        "W_%=:\n"
        "mbarrier.try_wait.parity.acquire.cta.shared::cta.b64 P, [%0], %1, 0x989680;\n"
        "@P bra.uni D_%=;\n"
        "bra.uni W_%=;\n"
        "D_%=:\n}" :: "r"(addr), "r"(parity) : "memory");
}

// gelu via erf(x/sqrt2) = x*Q(x^2), 8-term Taylor (validated R10/R11).
__device__ __forceinline__ float gelu_poly(float x) {
    float t = x * x;
    float p = fmaf(t, -8.24550e-8f, 1.331920e-6f);
    p = fmaf(t, p, -1.888910e-5f);
    p = fmaf(t, p, 2.308700e-4f);
    p = fmaf(t, p, -2.3746565e-3f);
    p = fmaf(t, p, 1.9947114e-2f);
    p = fmaf(t, p, -0.13298076f);
    p = fmaf(t, p, 0.79788456f);
    float e  = x * p;
    float hx = 0.5f * x;
    return fmaf(hx, e, hx);
}

// Strides (words).
#define ASTR 36
#define BSTR 136
#define ASZW (128 * ASTR)     // 4608 words = 18432 B
#define BSZW (32 * BSTR)
#define NKT  (HID / 32)       // 32 k-tiles in phase 2
#define NKT1 (ED / 32)
#define NSTG1 3
#define P1_SMEM ((ASZW + NSTG1 * BSZW) * 4)           // 70656 B

// Phase 2 ring: 5 stages of (A tile + B tile), mbarriers in first 128 B.
#define NSTG2 5
#define STAGEB (2 * ASZW * 4)                          // 36864 B
#define P2_SMEM (128 + NSTG2 * STAGEB)                 // 184448 B

// ---------------------------------------------------------------------------
// Phase 1 (unchanged, known good): scalar-LDS 64x32 tiles + W2 transpose tail.
// ---------------------------------------------------------------------------
#define COMPUTE_TILE6432(Ap, Bp)                                                \
    _Pragma("unroll")                                                           \
    for (int ks = 0; ks < 4; ks++) {                                            \
        const int kk = ks * 8;                                                  \
        uint32_t af[4][4];                                                      \
        _Pragma("unroll")                                                       \
        for (int s = 0; s < 4; s++) {                                           \
            int r0 = wm + s * 16 + g;                                           \
            af[s][0] = (Ap)[r0 * ASTR + kk + tg];                               \
            af[s][1] = (Ap)[(r0 + 8) * ASTR + kk + tg];                         \
            af[s][2] = (Ap)[r0 * ASTR + kk + 4 + tg];                           \
            af[s][3] = (Ap)[(r0 + 8) * ASTR + kk + 4 + tg];                     \
        }                                                                       \
        uint32_t bf[4][2];                                                      \
        _Pragma("unroll")                                                       \
        for (int q = 0; q < 4; q++) {                                           \
            int nb = wn + q * 8 + g;                                            \
            bf[q][0] = (Bp)[(kk + tg) * BSTR + nb];                             \
            bf[q][1] = (Bp)[(kk + 4 + tg) * BSTR + nb];                         \
        }                                                                       \
        _Pragma("unroll")                                                       \
        for (int s = 0; s < 4; s++)                                             \
            _Pragma("unroll")                                                   \
            for (int q = 0; q < 4; q++)                                         \
                mma8(c[s][q], af[s], bf[q]);                                    \
    }

__global__ __launch_bounds__(256, 2) void phase1_kernel(
    const float* __restrict__ El, const float* __restrict__ Er,
    const float* __restrict__ W1, const float* __restrict__ W2)
{
    extern __shared__ uint32_t dsm[];
    uint32_t* A_s = dsm;
    uint32_t* Bs  = dsm + ASZW;
    const uint32_t bs_base = smem_u32(Bs);

    const int nt = blockIdx.x, inst = blockIdx.y, side = blockIdx.z;
    const float* E   = (side ? Er : El) + inst * NVOCAB * ED;
    float*       Hst = (side ? g_HR : g_HL) + inst * NVOCAB * HID + nt * 128;
    const float* W   = W1 + inst * ED * HID + nt * 128;

    const int t    = threadIdx.x;
    const int lane = t & 31, w = t >> 5;
    const int wm = (w & 1) * 64, wn = (w >> 1) * 32;
    const int g = lane >> 2, tg = lane & 3;
    const int r0a = t >> 2, c8 = (t & 3) * 8;

    float c[4][4][4];
#pragma unroll
    for (int s = 0; s < 4; s++)
#pragma unroll
        for (int q = 0; q < 4; q++)
#pragma unroll
            for (int v = 0; v < 4; v++) c[s][q][v] = 0.f;

#define PREFETCH_B1(KT) do {                                                    \
        if ((KT) < NKT1) {                                                      \
            const uint32_t bb = bs_base + (uint32_t)((((KT) % NSTG1)) * (BSZW * 4)); \
            const float* srcb = W + (size_t)(KT) * 32 * HID;                    \
            _Pragma("unroll")                                                   \
            for (int j = 0; j < 4; j++) {                                       \
                int cc = t + 256 * j;                                           \
                int k = cc >> 5, nc = (cc & 31) * 4;                            \
                uint32_t dst = bb + (uint32_t)(k * BSTR + nc) * 4;              \
                const float* src = srcb + (size_t)k * HID + nc;                 \
                asm volatile("cp.async.cg.shared.global [%0], [%1], 16;"        \
                             :: "r"(dst), "l"(src) : "memory");                 \
            }                                                                   \
        }                                                                       \
        asm volatile("cp.async.commit_group;" ::: "memory");                    \
    } while (0)

    PREFETCH_B1(0); PREFETCH_B1(1); PREFETCH_B1(2);

#pragma unroll 1
    for (int kt = 0; kt < NKT1; kt++) {
        const int k0 = kt * 32;
#pragma unroll
        for (int j = 0; j < 2; j++) {
            int row = r0a + 64 * j;
            float4 v0 = *reinterpret_cast<const float4*>(E + row * ED + k0 + c8);
            float4 v1 = *reinterpret_cast<const float4*>(E + row * ED + k0 + c8 + 4);
            *reinterpret_cast<uint4*>(&A_s[row * ASTR + c8]) =
                make_uint4(f2tf(v0.x), f2tf(v0.y), f2tf(v0.z), f2tf(v0.w));
            *reinterpret_cast<uint4*>(&A_s[row * ASTR + c8 + 4]) =
                make_uint4(f2tf(v1.x), f2tf(v1.y), f2tf(v1.z), f2tf(v1.w));
        }
        asm volatile("cp.async.wait_group %0;" :: "n"(NSTG1 - 1) : "memory");
        __syncthreads();

        uint32_t* Bp = Bs + (kt % NSTG1) * BSZW;
#pragma unroll
        for (int j = 0; j < 4; j++) {
            int cc = t + 256 * j;
            int k = cc >> 5, nc = (cc & 31) * 4;
            uint4* p = reinterpret_cast<uint4*>(&Bp[k * BSTR + nc]);
            uint4 u = *p;
            u.x = f2tf(__uint_as_float(u.x));
            u.y = f2tf(__uint_as_float(u.y));
            u.z = f2tf(__uint_as_float(u.z));
            u.w = f2tf(__uint_as_float(u.w));
            *p = u;
        }
        __syncthreads();
        COMPUTE_TILE6432(A_s, Bp);
        __syncthreads();
        PREFETCH_B1(kt + NSTG1);
    }

#pragma unroll
    for (int s = 0; s < 4; s++) {
        int row = wm + s * 16 + g;
#pragma unroll
        for (int q = 0; q < 4; q++) {
            int col = wn + q * 8 + 2 * tg;
            *reinterpret_cast<float2*>(Hst + row * HID + col) =
                make_float2(c[s][q][0], c[s][q][1]);
            *reinterpret_cast<float2*>(Hst + (row + 8) * HID + col) =
                make_float2(c[s][q][2], c[s][q][3]);
        }
    }

    // Tail: transpose + tf32 W2 [i][k][n] -> g_W2t [i][n][k], 8 tiles/CTA.
    {
        float* tsm = reinterpret_cast<float*>(dsm);   // 32x33 tile
        const int ci = ((blockIdx.z * INST + blockIdx.y) * (HID / 128)
                        + blockIdx.x);                 // 0..1023
        const int ty = t >> 5, tx = t & 31;
#pragma unroll 1
        for (int j = 0; j < 8; j++) {
            const int tt = ci * 8 + j;                 // 0..8191
            const int i  = tt >> 7;
            const int rem = tt & 127;
            const int kt32 = rem >> 2, nt32 = rem & 3;
            __syncthreads();
#pragma unroll
            for (int jj = 0; jj < 4; jj++) {
                int kk = ty + 8 * jj;
                tsm[kk * 33 + tx] =
                    W2[((size_t)i * HID + kt32 * 32 + kk) * NVOCAB + nt32 * 32 + tx];
            }
            __syncthreads();
#pragma unroll
            for (int jj = 0; jj < 4; jj++) {
                int nn = ty + 8 * jj;
                g_W2t[((size_t)i * NVOCAB + nt32 * 32 + nn) * HID + kt32 * 32 + tx] =
                    f2tf(tsm[tx * 33 + nn]);
            }
        }
    }
}

// ---------------------------------------------------------------------------
// Phase 2: WARP-SPECIALIZED. 512 threads: warps 0-7 consumers (LDSM+MMA),
// warps 8-15 producers (gather+gelu+STS A, cp.async B). 5-stage ring,
// mbarrier full/empty per stage. grid (16, 64), 1 CTA/SM (184 KB smem).
// ---------------------------------------------------------------------------
__global__ __launch_bounds__(512, 1) void phase2_kernel(
    const int* __restrict__ a, float* __restrict__ out)
{
    extern __shared__ uint32_t dsm[];
    const uint32_t sbase = smem_u32(dsm);
    const uint32_t stg0  = sbase + 128;
    // full[s] = sbase + s*16 ; empty[s] = sbase + s*16 + 8

    const int t = threadIdx.x;
    const int mt = blockIdx.x, inst = blockIdx.y;

    if (t == 0) {
#pragma unroll
        for (int s = 0; s < NSTG2; s++) {
            MBAR_INIT(sbase + s * 16, 256);       // full: 256 producer arrivals
            MBAR_INIT(sbase + s * 16 + 8, 256);   // empty: 256 consumer arrivals
        }
    }
    __syncthreads();

    if (t < 256) {
        // ===================== CONSUMER =====================
        const int lane = t & 31, w = t >> 5;
        const int wm = (w & 1) * 64, wn = (w >> 1) * 32;
        const int g = lane >> 2, tg = lane & 3;
        const int qm = lane >> 3, rm = lane & 7;

        uint32_t aoff[4];
#pragma unroll
        for (int s = 0; s < 4; s++) {
            int arow = wm + s * 16 + (qm & 1) * 8 + rm;
            aoff[s] = (uint32_t)(arow * ASTR + (qm >> 1) * 4) * 4;
        }
        const uint32_t boff0 = (uint32_t)((wn + (qm >> 1) * 8 + rm) * ASTR + (qm & 1) * 4) * 4;
        const uint32_t boff1 = boff0 + 16 * ASTR * 4;

        float c[4][4][4];
#pragma unroll
        for (int s = 0; s < 4; s++)
#pragma unroll
            for (int q = 0; q < 4; q++)
#pragma unroll
                for (int v = 0; v < 4; v++) c[s][q][v] = 0.f;

        int st = 0, ph = 0;
#pragma unroll 1
        for (int kt = 0; kt < NKT; kt++) {
            mbar_wait(sbase + st * 16, ph);           // full[st]
            const uint32_t abB = stg0 + (uint32_t)st * STAGEB;
            const uint32_t bbB = abB + ASZW * 4;
#pragma unroll
            for (int ks = 0; ks < 4; ks++) {
                const uint32_t kkB = (uint32_t)(ks * 32);
                uint32_t af[4][4], b0[4], b1[4];
                ldsm4(af[0][0], af[0][1], af[0][2], af[0][3], abB + aoff[0] + kkB);
                ldsm4(af[1][0], af[1][1], af[1][2], af[1][3], abB + aoff[1] + kkB);
                ldsm4(af[2][0], af[2][1], af[2][2], af[2][3], abB + aoff[2] + kkB);
                ldsm4(af[3][0], af[3][1], af[3][2], af[3][3], abB + aoff[3] + kkB);
                ldsm4(b0[0], b0[1], b0[2], b0[3], bbB + boff0 + kkB);
                ldsm4(b1[0], b1[1], b1[2], b1[3], bbB + boff1 + kkB);
#pragma unroll
                for (int s = 0; s < 4; s++) {
                    mma8(c[s][0], af[s], &b0[0]);
                    mma8(c[s][1], af[s], &b0[2]);
                    mma8(c[s][2], af[s], &b1[0]);
                    mma8(c[s][3], af[s], &b1[2]);
                }
            }
            MBAR_ARRIVE(sbase + st * 16 + 8);         // empty[st]
            if (++st == NSTG2) { st = 0; ph ^= 1; }
        }

        // Epilogue: out shape (BATCH, INST, NVOCAB) fp32
#pragma unroll
        for (int s = 0; s < 4; s++) {
            int rowb = mt * 128 + wm + s * 16 + g;
#pragma unroll
            for (int q = 0; q < 4; q++) {
                int col = wn + q * 8 + 2 * tg;
                *reinterpret_cast<float2*>(out + ((size_t)rowb * INST + inst) * NVOCAB + col) =
                    make_float2(c[s][q][0], c[s][q][1]);
                *reinterpret_cast<float2*>(out + ((size_t)(rowb + 8) * INST + inst) * NVOCAB + col) =
                    make_float2(c[s][q][2], c[s][q][3]);
            }
        }
    } else {
        // ===================== PRODUCER =====================
        const int pt = t - 256;
        const int row = pt >> 1, h = pt & 1;   // one A row, 16-col half
        const int b = mt * 128 + row;
        const int i1 = a[2 * b], i2 = a[2 * b + 1];
        const float* pL = g_HL + ((size_t)inst * NVOCAB + i1) * HID + h * 16;
        const float* pR = g_HR + ((size_t)inst * NVOCAB + i2) * HID + h * 16;
        const uint32_t* Wt = g_W2t + (size_t)inst * NVOCAB * HID;
        const uint32_t asts = (uint32_t)(row * ASTR + h * 16) * 4;  // byte off in A tile

        float4 sA[4];
#define P2_LDGSUM(KT) do {                                                      \
            const int k0 = (KT) * 32;                                           \
            _Pragma("unroll")                                                   \
            for (int j = 0; j < 4; j++) {                                       \
                float4 l = *reinterpret_cast<const float4*>(pL + k0 + 4 * j);   \
                float4 r = *reinterpret_cast<const float4*>(pR + k0 + 4 * j);   \
                sA[j] = make_float4(l.x + r.x, l.y + r.y, l.z + r.z, l.w + r.w);\
            }                                                                   \
        } while (0)

        P2_LDGSUM(0);

        int st = 0, ph = 1;                     // empty-waits pass on fresh barriers
#pragma unroll 1
        for (int kt = 0; kt < NKT; kt++) {
            mbar_wait(sbase + st * 16 + 8, ph);       // empty[st]
            const uint32_t abB = stg0 + (uint32_t)st * STAGEB;
            const uint32_t bbB = abB + ASZW * 4;

            // B(kt) via cp.async: 4 x uint4 per thread (1024 total)
            {
                const uint32_t* srcb = Wt + (size_t)kt * 32;
#pragma unroll
                for (int j = 0; j < 4; j++) {
                    int cc = pt + 256 * j;
                    int nrow = cc >> 3, kc = (cc & 7) * 4;
                    uint32_t dst = bbB + (uint32_t)(nrow * ASTR + kc) * 4;
                    const uint32_t* src = srcb + (size_t)nrow * HID + kc;
                    asm volatile("cp.async.cg.shared.global [%0], [%1], 16;"
                                 :: "r"(dst), "l"(src) : "memory");
                }
                asm volatile("cp.async.commit_group;" ::: "memory");
            }

            // A(kt): gelu + STS from staged sums
            {
                uint4 u0, u1;
                u0.x = f2tf(gelu_poly(sA[0].x));
                u0.y = f2tf(gelu_poly(sA[0].y));
                u0.z = f2tf(gelu_poly(sA[0].z));
                u0.w = f2tf(gelu_poly(sA[0].w));
                u1.x = f2tf(gelu_poly(sA[1].x));
                u1.y = f2tf(gelu_poly(sA[1].y));
                u1.z = f2tf(gelu_poly(sA[1].z));
                u1.w = f2tf(gelu_poly(sA[1].w));
                *reinterpret_cast<uint4*>((char*)dsm + (abB - sbase) + asts) = u0;
                *reinterpret_cast<uint4*>((char*)dsm + (abB - sbase) + asts + 16) = u1;
                u0.x = f2tf(gelu_poly(sA[2].x));
                u0.y = f2tf(gelu_poly(sA[2].y));
                u0.z = f2tf(gelu_poly(sA[2].z));
                u0.w = f2tf(gelu_poly(sA[2].w));
                u1.x = f2tf(gelu_poly(sA[3].x));
                u1.y = f2tf(gelu_poly(sA[3].y));
                u1.z = f2tf(gelu_poly(sA[3].z));
                u1.w = f2tf(gelu_poly(sA[3].w));
                *reinterpret_cast<uint4*>((char*)dsm + (abB - sbase) + asts + 32) = u0;
                *reinterpret_cast<uint4*>((char*)dsm + (abB - sbase) + asts + 48) = u1;
            }

            if (kt + 1 < NKT) P2_LDGSUM(kt + 1);

            // Signal full for tile kt-2 (its B is complete after wait_group 2,
            // its A STS happened 2 iterations ago in this same thread).
            if (kt >= 2) {
                asm volatile("cp.async.wait_group 2;" ::: "memory");
                MBAR_ARRIVE(sbase + ((kt - 2) % NSTG2) * 16);
            }
            if (++st == NSTG2) { st = 0; ph ^= 1; }
        }
        asm volatile("cp.async.wait_group 1;" ::: "memory");
        MBAR_ARRIVE(sbase + ((NKT - 2) % NSTG2) * 16);
        asm volatile("cp.async.wait_group 0;" ::: "memory");
        MBAR_ARRIVE(sbase + ((NKT - 1) % NSTG2) * 16);
#undef P2_LDGSUM
    }
}

// ---------------------------------------------------------------------------
extern "C" void kernel_launch(void* const* d_in, const int* in_sizes, int n_in,
                              void* d_out, int out_size)
{
    const int*   a  = (const int*)d_in[0];
    const float* El = (const float*)d_in[1];
    const float* Er = (const float*)d_in[2];
    const float* W1 = (const float*)d_in[3];
    const float* W2 = (const float*)d_in[4];
    float* out = (float*)d_out;

    static int configured = 0;
    if (!configured) {
        cudaFuncSetAttribute(phase1_kernel,
                             cudaFuncAttributeMaxDynamicSharedMemorySize, P1_SMEM);
        cudaFuncSetAttribute(phase2_kernel,
                             cudaFuncAttributeMaxDynamicSharedMemorySize, P2_SMEM);
        configured = 1;
    }

    dim3 g1(HID / 128, INST, 2);
    phase1_kernel<<<g1, 256, P1_SMEM>>>(El, Er, W1, W2);

    dim3 g2(BATCH / 128, INST);
    phase2_kernel<<<g2, 512, P2_SMEM>>>(a, out);
}

// round 13
// speedup vs baseline: 1.3896x; 1.3896x over previous
#include <cuda_runtime.h>
#include <cuda_bf16.h>
#include <cstdint>
#include <math.h>

#define INST   64
#define NVOCAB 128
#define ED     256
#define HID    1024
#define BATCH  2048

// Precomputed HL[i] = E_l[i] @ W1[i], HR[i] = E_r[i] @ W1[i]  (fp32 scratch)
__device__ float g_HL[INST * NVOCAB * HID];
__device__ float g_HR[INST * NVOCAB * HID];
// W2 transposed + tf32: [inst][n][k]  (filled by phase1 tail)
__device__ uint32_t g_W2t[INST * NVOCAB * HID];

__device__ __forceinline__ uint32_t f2tf(float f) {
    uint32_t u;
    asm("cvt.rna.tf32.f32 %0, %1;" : "=r"(u) : "f"(f));
    return u;
}
__device__ __forceinline__ void mma8(float* c, const uint32_t* a, const uint32_t* b) {
    asm volatile(
        "mma.sync.aligned.m16n8k8.row.col.f32.tf32.tf32.f32 "
        "{%0,%1,%2,%3}, {%4,%5,%6,%7}, {%8,%9}, {%0,%1,%2,%3};"
        : "+f"(c[0]), "+f"(c[1]), "+f"(c[2]), "+f"(c[3])
        : "r"(a[0]), "r"(a[1]), "r"(a[2]), "r"(a[3]), "r"(b[0]), "r"(b[1]));
}
__device__ __forceinline__ void ldsm4(uint32_t& r0, uint32_t& r1, uint32_t& r2,
                                      uint32_t& r3, uint32_t addr) {
    asm volatile("ldmatrix.sync.aligned.m8n8.x4.shared.b16 {%0,%1,%2,%3}, [%4];"
                 : "=r"(r0), "=r"(r1), "=r"(r2), "=r"(r3) : "r"(addr));
}
__device__ __forceinline__ uint32_t smem_u32(const void* p) {
    uint32_t a;
    asm("{ .reg .u64 t; cvta.to.shared.u64 t, %1; cvt.u32.u64 %0, t; }" : "=r"(a) : "l"(p));
    return a;
}

// gelu via erf(x/sqrt2) = x*Q(x^2), 8-term Taylor (validated R10/R11).
__device__ __forceinline__ float gelu_poly(float x) {
    float t = x * x;
    float p = fmaf(t, -8.24550e-8f, 1.331920e-6f);
    p = fmaf(t, p, -1.888910e-5f);
    p = fmaf(t, p, 2.308700e-4f);
    p = fmaf(t, p, -2.3746565e-3f);
    p = fmaf(t, p, 1.9947114e-2f);
    p = fmaf(t, p, -0.13298076f);
    p = fmaf(t, p, 0.79788456f);
    float e  = x * p;
    float hx = 0.5f * x;
    return fmaf(hx, e, hx);
}

// Strides (words).
#define ASTR 36
#define BSTR 136
#define ASZW (128 * ASTR)     // phase1 A tile: 4608 words
#define BSZW (32 * BSTR)
#define NKT  (HID / 32)       // 32 k-tiles in phase 2
#define NKT1 (ED / 32)
#define NSTG1 3
#define P1_SMEM ((ASZW + NSTG1 * BSZW) * 4)           // 70656 B

// Phase 2: 128-thread CTA, tile 64x128. A tile 64x36 w, B tile 128x36 w.
#define A2SZW (64 * ASTR)      // 2304 words
#define B2SZW (128 * ASTR)     // 4608 words
#define P2_SMEM ((2 * A2SZW + 2 * B2SZW) * 4)         // 55296 B -> 4 CTAs/SM

// ---------------------------------------------------------------------------
// Phase 1 (unchanged, known good): scalar-LDS 64x32 tiles + W2 transpose tail.
// ---------------------------------------------------------------------------
#define COMPUTE_TILE6432(Ap, Bp)                                                \
    _Pragma("unroll")                                                           \
    for (int ks = 0; ks < 4; ks++) {                                            \
        const int kk = ks * 8;                                                  \
        uint32_t af[4][4];                                                      \
        _Pragma("unroll")                                                       \
        for (int s = 0; s < 4; s++) {                                           \
            int r0 = wm + s * 16 + g;                                           \
            af[s][0] = (Ap)[r0 * ASTR + kk + tg];                               \
            af[s][1] = (Ap)[(r0 + 8) * ASTR + kk + tg];                         \
            af[s][2] = (Ap)[r0 * ASTR + kk + 4 + tg];                           \
            af[s][3] = (Ap)[(r0 + 8) * ASTR + kk + 4 + tg];                     \
        }                                                                       \
        uint32_t bf[4][2];                                                      \
        _Pragma("unroll")                                                       \
        for (int q = 0; q < 4; q++) {                                           \
            int nb = wn + q * 8 + g;                                            \
            bf[q][0] = (Bp)[(kk + tg) * BSTR + nb];                             \
            bf[q][1] = (Bp)[(kk + 4 + tg) * BSTR + nb];                         \
        }                                                                       \
        _Pragma("unroll")                                                       \
        for (int s = 0; s < 4; s++)                                             \
            _Pragma("unroll")                                                   \
            for (int q = 0; q < 4; q++)                                         \
                mma8(c[s][q], af[s], bf[q]);                                    \
    }

__global__ __launch_bounds__(256, 2) void phase1_kernel(
    const float* __restrict__ El, const float* __restrict__ Er,
    const float* __restrict__ W1, const float* __restrict__ W2)
{
    extern __shared__ uint32_t dsm[];
    uint32_t* A_s = dsm;
    uint32_t* Bs  = dsm + ASZW;
    const uint32_t bs_base = smem_u32(Bs);

    const int nt = blockIdx.x, inst = blockIdx.y, side = blockIdx.z;
    const float* E   = (side ? Er : El) + inst * NVOCAB * ED;
    float*       Hst = (side ? g_HR : g_HL) + inst * NVOCAB * HID + nt * 128;
    const float* W   = W1 + inst * ED * HID + nt * 128;

    const int t    = threadIdx.x;
    const int lane = t & 31, w = t >> 5;
    const int wm = (w & 1) * 64, wn = (w >> 1) * 32;
    const int g = lane >> 2, tg = lane & 3;
    const int r0a = t >> 2, c8 = (t & 3) * 8;

    float c[4][4][4];
#pragma unroll
    for (int s = 0; s < 4; s++)
#pragma unroll
        for (int q = 0; q < 4; q++)
#pragma unroll
            for (int v = 0; v < 4; v++) c[s][q][v] = 0.f;

#define PREFETCH_B1(KT) do {                                                    \
        if ((KT) < NKT1) {                                                      \
            const uint32_t bb = bs_base + (uint32_t)((((KT) % NSTG1)) * (BSZW * 4)); \
            const float* srcb = W + (size_t)(KT) * 32 * HID;                    \
            _Pragma("unroll")                                                   \
            for (int j = 0; j < 4; j++) {                                       \
                int cc = t + 256 * j;                                           \
                int k = cc >> 5, nc = (cc & 31) * 4;                            \
                uint32_t dst = bb + (uint32_t)(k * BSTR + nc) * 4;              \
                const float* src = srcb + (size_t)k * HID + nc;                 \
                asm volatile("cp.async.cg.shared.global [%0], [%1], 16;"        \
                             :: "r"(dst), "l"(src) : "memory");                 \
            }                                                                   \
        }                                                                       \
        asm volatile("cp.async.commit_group;" ::: "memory");                    \
    } while (0)

    PREFETCH_B1(0); PREFETCH_B1(1); PREFETCH_B1(2);

#pragma unroll 1
    for (int kt = 0; kt < NKT1; kt++) {
        const int k0 = kt * 32;
#pragma unroll
        for (int j = 0; j < 2; j++) {
            int row = r0a + 64 * j;
            float4 v0 = *reinterpret_cast<const float4*>(E + row * ED + k0 + c8);
            float4 v1 = *reinterpret_cast<const float4*>(E + row * ED + k0 + c8 + 4);
            *reinterpret_cast<uint4*>(&A_s[row * ASTR + c8]) =
                make_uint4(f2tf(v0.x), f2tf(v0.y), f2tf(v0.z), f2tf(v0.w));
            *reinterpret_cast<uint4*>(&A_s[row * ASTR + c8 + 4]) =
                make_uint4(f2tf(v1.x), f2tf(v1.y), f2tf(v1.z), f2tf(v1.w));
        }
        asm volatile("cp.async.wait_group %0;" :: "n"(NSTG1 - 1) : "memory");
        __syncthreads();

        uint32_t* Bp = Bs + (kt % NSTG1) * BSZW;
#pragma unroll
        for (int j = 0; j < 4; j++) {
            int cc = t + 256 * j;
            int k = cc >> 5, nc = (cc & 31) * 4;
            uint4* p = reinterpret_cast<uint4*>(&Bp[k * BSTR + nc]);
            uint4 u = *p;
            u.x = f2tf(__uint_as_float(u.x));
            u.y = f2tf(__uint_as_float(u.y));
            u.z = f2tf(__uint_as_float(u.z));
            u.w = f2tf(__uint_as_float(u.w));
            *p = u;
        }
        __syncthreads();
        COMPUTE_TILE6432(A_s, Bp);
        __syncthreads();
        PREFETCH_B1(kt + NSTG1);
    }

#pragma unroll
    for (int s = 0; s < 4; s++) {
        int row = wm + s * 16 + g;
#pragma unroll
        for (int q = 0; q < 4; q++) {
            int col = wn + q * 8 + 2 * tg;
            *reinterpret_cast<float2*>(Hst + row * HID + col) =
                make_float2(c[s][q][0], c[s][q][1]);
            *reinterpret_cast<float2*>(Hst + (row + 8) * HID + col) =
                make_float2(c[s][q][2], c[s][q][3]);
        }
    }

    // Tail: transpose + tf32 W2 [i][k][n] -> g_W2t [i][n][k], 8 tiles/CTA.
    {
        float* tsm = reinterpret_cast<float*>(dsm);   // 32x33 tile
        const int ci = ((blockIdx.z * INST + blockIdx.y) * (HID / 128)
                        + blockIdx.x);                 // 0..1023
        const int ty = t >> 5, tx = t & 31;
#pragma unroll 1
        for (int j = 0; j < 8; j++) {
            const int tt = ci * 8 + j;                 // 0..8191
            const int i  = tt >> 7;
            const int rem = tt & 127;
            const int kt32 = rem >> 2, nt32 = rem & 3;
            __syncthreads();
#pragma unroll
            for (int jj = 0; jj < 4; jj++) {
                int kk = ty + 8 * jj;
                tsm[kk * 33 + tx] =
                    W2[((size_t)i * HID + kt32 * 32 + kk) * NVOCAB + nt32 * 32 + tx];
            }
            __syncthreads();
#pragma unroll
            for (int jj = 0; jj < 4; jj++) {
                int nn = ty + 8 * jj;
                g_W2t[((size_t)i * NVOCAB + nt32 * 32 + nn) * HID + kt32 * 32 + tx] =
                    f2tf(tsm[tx * 33 + nn]);
            }
        }
    }
}

// ---------------------------------------------------------------------------
// Phase 2: out[b,i,:] = gelu(HL[i,a1[b],:] + HR[i,a2[b],:]) @ W2[i]
// 128-thread CTAs, tile 64x128, 4 CTAs/SM (4 independent pipelines/SMSP).
// A+B double-buffered, prefetch distance = 1 iter, one sync per iter.
// grid (32 m-tiles, 64 instances).
// ---------------------------------------------------------------------------
__global__ __launch_bounds__(128, 4) void phase2_kernel(
    const int* __restrict__ a, float* __restrict__ out)
{
    extern __shared__ uint32_t dsm[];
    // Layout: A0, A1 (64x36 each), B0, B1 (128x36 each)
    uint32_t* Ab[2] = { dsm, dsm + A2SZW };
    const uint32_t abase0 = smem_u32(dsm);
    const uint32_t bbase  = abase0 + 2 * A2SZW * 4;

    const int mt = blockIdx.x, inst = blockIdx.y;
    const uint32_t* Wt = g_W2t + (size_t)inst * NVOCAB * HID;  // [n][k]

    const int t    = threadIdx.x;
    const int lane = t & 31, w = t >> 5;
    const int wn = w * 32;                 // wm = 0 (all warps share M=64)
    const int g = lane >> 2, tg = lane & 3;

    // A producer: 2 threads/row, row = t>>1 (0..63), half h = t&1 (16 floats)
    const int row = t >> 1, h = t & 1;

    // ldmatrix per-lane offsets (bytes within a tile).
    const int qm = lane >> 3, rm = lane & 7;
    uint32_t aoff[4];
#pragma unroll
    for (int s = 0; s < 4; s++) {
        int arow = s * 16 + (qm & 1) * 8 + rm;
        aoff[s] = (uint32_t)(arow * ASTR + (qm >> 1) * 4) * 4;
    }
    const uint32_t boff0 = (uint32_t)((wn + (qm >> 1) * 8 + rm) * ASTR + (qm & 1) * 4) * 4;
    const uint32_t boff1 = boff0 + 16 * ASTR * 4;

    // Gather offsets for this thread's single A row.
    const int b = mt * 64 + row;
    const int i1 = a[2 * b], i2 = a[2 * b + 1];
    const float* pL = g_HL + ((size_t)inst * NVOCAB + i1) * HID + h * 16;
    const float* pR = g_HR + ((size_t)inst * NVOCAB + i2) * HID + h * 16;
    const uint32_t asts = (uint32_t)(row * ASTR + h * 16);   // word offset in A tile

    float c[4][4][4];
#pragma unroll
    for (int s = 0; s < 4; s++)
#pragma unroll
        for (int q = 0; q < 4; q++)
#pragma unroll
            for (int v = 0; v < 4; v++) c[s][q][v] = 0.f;

    float4 sA[4];

#define LDGSUM(KT) do {                                                         \
        const int k0 = (KT) * 32;                                               \
        _Pragma("unroll")                                                       \
        for (int j = 0; j < 4; j++) {                                           \
            float4 l = *reinterpret_cast<const float4*>(pL + k0 + 4 * j);       \
            float4 r = *reinterpret_cast<const float4*>(pR + k0 + 4 * j);       \
            sA[j] = make_float4(l.x + r.x, l.y + r.y, l.z + r.z, l.w + r.w);    \
        }                                                                       \
    } while (0)

#define GELUSTS(Ap) do {                                                        \
        uint4 u0, u1;                                                           \
        u0.x = f2tf(gelu_poly(sA[0].x));                                        \
        u0.y = f2tf(gelu_poly(sA[0].y));                                        \
        u0.z = f2tf(gelu_poly(sA[0].z));                                        \
        u0.w = f2tf(gelu_poly(sA[0].w));                                        \
        u1.x = f2tf(gelu_poly(sA[1].x));                                        \
        u1.y = f2tf(gelu_poly(sA[1].y));                                        \
        u1.z = f2tf(gelu_poly(sA[1].z));                                        \
        u1.w = f2tf(gelu_poly(sA[1].w));                                        \
        *reinterpret_cast<uint4*>(&(Ap)[asts]) = u0;                            \
        *reinterpret_cast<uint4*>(&(Ap)[asts + 4]) = u1;                        \
        u0.x = f2tf(gelu_poly(sA[2].x));                                        \
        u0.y = f2tf(gelu_poly(sA[2].y));                                        \
        u0.z = f2tf(gelu_poly(sA[2].z));                                        \
        u0.w = f2tf(gelu_poly(sA[2].w));                                        \
        u1.x = f2tf(gelu_poly(sA[3].x));                                        \
        u1.y = f2tf(gelu_poly(sA[3].y));                                        \
        u1.z = f2tf(gelu_poly(sA[3].z));                                        \
        u1.w = f2tf(gelu_poly(sA[3].w));                                        \
        *reinterpret_cast<uint4*>(&(Ap)[asts + 8]) = u0;                        \
        *reinterpret_cast<uint4*>(&(Ap)[asts + 12]) = u1;                       \
    } while (0)

    // B prefetch: 128 n-rows x 32 k-words = 1024 uint4 / 128 thr = 8 each.
#define PREFETCH_B2(KT) do {                                                    \
        if ((KT) < NKT) {                                                       \
            const uint32_t bb = bbase + (uint32_t)(((KT) & 1) * (B2SZW * 4));   \
            const uint32_t* srcb = Wt + (size_t)(KT) * 32;                      \
            _Pragma("unroll")                                                   \
            for (int j = 0; j < 8; j++) {                                       \
                int cc = t + 128 * j;                                           \
                int nrow = cc >> 3, kc = (cc & 7) * 4;                          \
                uint32_t dst = bb + (uint32_t)(nrow * ASTR + kc) * 4;           \
                const uint32_t* src = srcb + (size_t)nrow * HID + kc;           \
                asm volatile("cp.async.cg.shared.global [%0], [%1], 16;"        \
                             :: "r"(dst), "l"(src) : "memory");                 \
            }                                                                   \
        }                                                                       \
        asm volatile("cp.async.commit_group;" ::: "memory");                    \
    } while (0)

    // Prologue: A(0) -> buf0, A(1) staged in regs, B(0) in flight.
    LDGSUM(0);
    GELUSTS(Ab[0]);
    LDGSUM(1);
    PREFETCH_B2(0);

#pragma unroll 1
    for (int kt = 0; kt < NKT; kt++) {
        asm volatile("cp.async.wait_group 0;" ::: "memory");  // B(kt) landed
        __syncthreads();   // B(kt)+A(kt) visible; all reads of slot (kt+1)&1 closed

        PREFETCH_B2(kt + 1);   // into slot (kt+1)&1 (readers finished iter kt-1)

        const uint32_t abB = abase0 + (uint32_t)((kt & 1) * (A2SZW * 4));
        const uint32_t bbB = bbase + (uint32_t)((kt & 1) * (B2SZW * 4));
#pragma unroll
        for (int ks = 0; ks < 4; ks++) {
            const uint32_t kkB = (uint32_t)(ks * 32);
            uint32_t af[4][4], b0[4], b1[4];
            ldsm4(af[0][0], af[0][1], af[0][2], af[0][3], abB + aoff[0] + kkB);
            ldsm4(af[1][0], af[1][1], af[1][2], af[1][3], abB + aoff[1] + kkB);
            ldsm4(af[2][0], af[2][1], af[2][2], af[2][3], abB + aoff[2] + kkB);
            ldsm4(af[3][0], af[3][1], af[3][2], af[3][3], abB + aoff[3] + kkB);
            ldsm4(b0[0], b0[1], b0[2], b0[3], bbB + boff0 + kkB);
            ldsm4(b1[0], b1[1], b1[2], b1[3], bbB + boff1 + kkB);
#pragma unroll
            for (int s = 0; s < 4; s++) {
                mma8(c[s][0], af[s], &b0[0]);
                mma8(c[s][1], af[s], &b0[2]);
                mma8(c[s][2], af[s], &b1[0]);
                mma8(c[s][3], af[s], &b1[2]);
            }
        }

        if (kt + 1 < NKT) GELUSTS(Ab[(kt + 1) & 1]);   // uses sums staged last iter
        if (kt + 2 < NKT) LDGSUM(kt + 2);              // hides under next iter
    }

    // Epilogue: out shape (BATCH, INST, NVOCAB) fp32
#pragma unroll
    for (int s = 0; s < 4; s++) {
        int rowb = mt * 64 + s * 16 + g;
#pragma unroll
        for (int q = 0; q < 4; q++) {
            int col = wn + q * 8 + 2 * tg;
            *reinterpret_cast<float2*>(out + ((size_t)rowb * INST + inst) * NVOCAB + col) =
                make_float2(c[s][q][0], c[s][q][1]);
            *reinterpret_cast<float2*>(out + ((size_t)(rowb + 8) * INST + inst) * NVOCAB + col) =
                make_float2(c[s][q][2], c[s][q][3]);
        }
    }
}

// ---------------------------------------------------------------------------
extern "C" void kernel_launch(void* const* d_in, const int* in_sizes, int n_in,
                              void* d_out, int out_size)
{
    const int*   a  = (const int*)d_in[0];
    const float* El = (const float*)d_in[1];
    const float* Er = (const float*)d_in[2];
    const float* W1 = (const float*)d_in[3];
    const float* W2 = (const float*)d_in[4];
    float* out = (float*)d_out;

    static int configured = 0;
    if (!configured) {
        cudaFuncSetAttribute(phase1_kernel,
                             cudaFuncAttributeMaxDynamicSharedMemorySize, P1_SMEM);
        cudaFuncSetAttribute(phase2_kernel,
                             cudaFuncAttributeMaxDynamicSharedMemorySize, P2_SMEM);
        configured = 1;
    }

    dim3 g1(HID / 128, INST, 2);
    phase1_kernel<<<g1, 256, P1_SMEM>>>(El, Er, W1, W2);

    dim3 g2(BATCH / 64, INST);
    phase2_kernel<<<g2, 128, P2_SMEM>>>(a, out);
}

// round 14
// speedup vs baseline: 1.4862x; 1.0695x over previous
#include <cuda_runtime.h>
#include <cuda_bf16.h>
#include <cstdint>
#include <math.h>

#define INST   64
#define NVOCAB 128
#define ED     256
#define HID    1024
#define BATCH  2048

// Precomputed HL[i] = E_l[i] @ W1[i], HR[i] = E_r[i] @ W1[i]  (fp32 scratch)
__device__ float g_HL[INST * NVOCAB * HID];
__device__ float g_HR[INST * NVOCAB * HID];
// W2 transposed + tf32: [inst][n][k]  (filled by phase1 tail)
__device__ uint32_t g_W2t[INST * NVOCAB * HID];

__device__ __forceinline__ uint32_t f2tf(float f) {
    uint32_t u;
    asm("cvt.rna.tf32.f32 %0, %1;" : "=r"(u) : "f"(f));
    return u;
}
__device__ __forceinline__ void mma8(float* c, const uint32_t* a, const uint32_t* b) {
    asm volatile(
        "mma.sync.aligned.m16n8k8.row.col.f32.tf32.tf32.f32 "
        "{%0,%1,%2,%3}, {%4,%5,%6,%7}, {%8,%9}, {%0,%1,%2,%3};"
        : "+f"(c[0]), "+f"(c[1]), "+f"(c[2]), "+f"(c[3])
        : "r"(a[0]), "r"(a[1]), "r"(a[2]), "r"(a[3]), "r"(b[0]), "r"(b[1]));
}
__device__ __forceinline__ void ldsm4(uint32_t& r0, uint32_t& r1, uint32_t& r2,
                                      uint32_t& r3, uint32_t addr) {
    asm volatile("ldmatrix.sync.aligned.m8n8.x4.shared.b16 {%0,%1,%2,%3}, [%4];"
                 : "=r"(r0), "=r"(r1), "=r"(r2), "=r"(r3) : "r"(addr));
}
__device__ __forceinline__ uint32_t smem_u32(const void* p) {
    uint32_t a;
    asm("{ .reg .u64 t; cvta.to.shared.u64 t, %1; cvt.u32.u64 %0, t; }" : "=r"(a) : "l"(p));
    return a;
}

// gelu via erf(x/sqrt2) = x*Q(x^2), 8-term Taylor (validated R10/R11).
__device__ __forceinline__ float gelu_poly(float x) {
    float t = x * x;
    float p = fmaf(t, -8.24550e-8f, 1.331920e-6f);
    p = fmaf(t, p, -1.888910e-5f);
    p = fmaf(t, p, 2.308700e-4f);
    p = fmaf(t, p, -2.3746565e-3f);
    p = fmaf(t, p, 1.9947114e-2f);
    p = fmaf(t, p, -0.13298076f);
    p = fmaf(t, p, 0.79788456f);
    float e  = x * p;
    float hx = 0.5f * x;
    return fmaf(hx, e, hx);
}

// Strides (words). ASTR used for A tiles AND phase2 B tiles (n-major, 128 rows).
#define ASTR 36
#define BSTR 136
#define ASZW (128 * ASTR)     // 4608 words = 18432 B
#define BSZW (32 * BSTR)      // 4352 words
#define NKT  (HID / 32)       // 32 k-tiles in phase 2
#define NKT1 (ED / 32)        // 8 k-tiles in phase 1
#define NSTG1 3
#define NSTG2 4
#define P1_SMEM ((ASZW + NSTG1 * BSZW) * 4)           // 70656 B
#define P2_SMEM ((2 + NSTG2) * ASZW * 4)              // 110592 B

// ---------------------------------------------------------------------------
// Phase 1: HL/HR[i] = E[i] (128x256) @ W1[i] (256x1024)
// B fragments converted to tf32 IN REGISTERS (no smem cvt pass, one less sync).
// 8-warp 64x32 tiles, cp.async B depth 3. grid (8, 64, 2), 256 threads.
// Tail: transpose + tf32 W2 into g_W2t.
// ---------------------------------------------------------------------------
__global__ __launch_bounds__(256, 2) void phase1_kernel(
    const float* __restrict__ El, const float* __restrict__ Er,
    const float* __restrict__ W1, const float* __restrict__ W2)
{
    extern __shared__ uint32_t dsm[];
    uint32_t* A_s = dsm;
    uint32_t* Bs  = dsm + ASZW;
    const uint32_t bs_base = smem_u32(Bs);

    const int nt = blockIdx.x, inst = blockIdx.y, side = blockIdx.z;
    const float* E   = (side ? Er : El) + inst * NVOCAB * ED;
    float*       Hst = (side ? g_HR : g_HL) + inst * NVOCAB * HID + nt * 128;
    const float* W   = W1 + inst * ED * HID + nt * 128;

    const int t    = threadIdx.x;
    const int lane = t & 31, w = t >> 5;
    const int wm = (w & 1) * 64, wn = (w >> 1) * 32;
    const int g = lane >> 2, tg = lane & 3;
    const int r0a = t >> 2, c8 = (t & 3) * 8;

    float c[4][4][4];
#pragma unroll
    for (int s = 0; s < 4; s++)
#pragma unroll
        for (int q = 0; q < 4; q++)
#pragma unroll
            for (int v = 0; v < 4; v++) c[s][q][v] = 0.f;

#define PREFETCH_B1(KT) do {                                                    \
        if ((KT) < NKT1) {                                                      \
            const uint32_t bb = bs_base + (uint32_t)((((KT) % NSTG1)) * (BSZW * 4)); \
            const float* srcb = W + (size_t)(KT) * 32 * HID;                    \
            _Pragma("unroll")                                                   \
            for (int j = 0; j < 4; j++) {                                       \
                int cc = t + 256 * j;                                           \
                int k = cc >> 5, nc = (cc & 31) * 4;                            \
                uint32_t dst = bb + (uint32_t)(k * BSTR + nc) * 4;              \
                const float* src = srcb + (size_t)k * HID + nc;                 \
                asm volatile("cp.async.cg.shared.global [%0], [%1], 16;"        \
                             :: "r"(dst), "l"(src) : "memory");                 \
            }                                                                   \
        }                                                                       \
        asm volatile("cp.async.commit_group;" ::: "memory");                    \
    } while (0)

    PREFETCH_B1(0); PREFETCH_B1(1); PREFETCH_B1(2);

#pragma unroll 1
    for (int kt = 0; kt < NKT1; kt++) {
        const int k0 = kt * 32;
        // Produce A tile (tf32 at produce time, as before)
#pragma unroll
        for (int j = 0; j < 2; j++) {
            int row = r0a + 64 * j;
            float4 v0 = *reinterpret_cast<const float4*>(E + row * ED + k0 + c8);
            float4 v1 = *reinterpret_cast<const float4*>(E + row * ED + k0 + c8 + 4);
            *reinterpret_cast<uint4*>(&A_s[row * ASTR + c8]) =
                make_uint4(f2tf(v0.x), f2tf(v0.y), f2tf(v0.z), f2tf(v0.w));
            *reinterpret_cast<uint4*>(&A_s[row * ASTR + c8 + 4]) =
                make_uint4(f2tf(v1.x), f2tf(v1.y), f2tf(v1.z), f2tf(v1.w));
        }
        asm volatile("cp.async.wait_group %0;" :: "n"(NSTG1 - 1) : "memory");
        __syncthreads();

        // Compute: B fragments converted fp32 -> tf32 in registers (rna,
        // element-wise => bit-identical to the old smem convert pass).
        const uint32_t* Bp = Bs + (kt % NSTG1) * BSZW;
#pragma unroll
        for (int ks = 0; ks < 4; ks++) {
            const int kk = ks * 8;
            uint32_t af[4][4];
#pragma unroll
            for (int s = 0; s < 4; s++) {
                int r0 = wm + s * 16 + g;
                af[s][0] = A_s[r0 * ASTR + kk + tg];
                af[s][1] = A_s[(r0 + 8) * ASTR + kk + tg];
                af[s][2] = A_s[r0 * ASTR + kk + 4 + tg];
                af[s][3] = A_s[(r0 + 8) * ASTR + kk + 4 + tg];
            }
            uint32_t bf[4][2];
#pragma unroll
            for (int q = 0; q < 4; q++) {
                int nb = wn + q * 8 + g;
                bf[q][0] = f2tf(__uint_as_float(Bp[(kk + tg) * BSTR + nb]));
                bf[q][1] = f2tf(__uint_as_float(Bp[(kk + 4 + tg) * BSTR + nb]));
            }
#pragma unroll
            for (int s = 0; s < 4; s++)
#pragma unroll
                for (int q = 0; q < 4; q++)
                    mma8(c[s][q], af[s], bf[q]);
        }
        __syncthreads();
        PREFETCH_B1(kt + NSTG1);
    }

#pragma unroll
    for (int s = 0; s < 4; s++) {
        int row = wm + s * 16 + g;
#pragma unroll
        for (int q = 0; q < 4; q++) {
            int col = wn + q * 8 + 2 * tg;
            *reinterpret_cast<float2*>(Hst + row * HID + col) =
                make_float2(c[s][q][0], c[s][q][1]);
            *reinterpret_cast<float2*>(Hst + (row + 8) * HID + col) =
                make_float2(c[s][q][2], c[s][q][3]);
        }
    }

    // Tail: transpose + tf32 W2 [i][k][n] -> g_W2t [i][n][k], 8 tiles/CTA.
    {
        float* tsm = reinterpret_cast<float*>(dsm);   // 32x33 tile
        const int ci = ((blockIdx.z * INST + blockIdx.y) * (HID / 128)
                        + blockIdx.x);                 // 0..1023
        const int ty = t >> 5, tx = t & 31;
#pragma unroll 1
        for (int j = 0; j < 8; j++) {
            const int tt = ci * 8 + j;                 // 0..8191
            const int i  = tt >> 7;
            const int rem = tt & 127;
            const int kt32 = rem >> 2, nt32 = rem & 3;
            __syncthreads();
#pragma unroll
            for (int jj = 0; jj < 4; jj++) {
                int kk = ty + 8 * jj;
                tsm[kk * 33 + tx] =
                    W2[((size_t)i * HID + kt32 * 32 + kk) * NVOCAB + nt32 * 32 + tx];
            }
            __syncthreads();
#pragma unroll
            for (int jj = 0; jj < 4; jj++) {
                int nn = ty + 8 * jj;
                g_W2t[((size_t)i * NVOCAB + nt32 * 32 + nn) * HID + kt32 * 32 + tx] =
                    f2tf(tsm[tx * 33 + nn]);
            }
        }
    }
}

// ---------------------------------------------------------------------------
// Phase 2 (byte-exact R10 config, best measured 272.6us):
// ldmatrix fragment loads (A row-major, B n-major), 8-term poly gelu,
// produce-ahead pipeline, B depth 4. grid (16, 64), 256 threads, 2 CTAs/SM.
// ---------------------------------------------------------------------------
__global__ __launch_bounds__(256, 2) void phase2_kernel(
    const int* __restrict__ a, float* __restrict__ out)
{
    extern __shared__ uint32_t dsm[];
    uint32_t* Ab[2] = { dsm, dsm + ASZW };
    const uint32_t abase0 = smem_u32(dsm);
    const uint32_t bbase  = abase0 + 2 * ASZW * 4;

    const int mt = blockIdx.x, inst = blockIdx.y;
    const uint32_t* Wt = g_W2t + (size_t)inst * NVOCAB * HID;  // [n][k]

    const int t    = threadIdx.x;
    const int lane = t & 31, w = t >> 5;
    const int wm = (w & 1) * 64, wn = (w >> 1) * 32;
    const int r0a = t >> 2, c8 = (t & 3) * 8;
    const int g = lane >> 2, tg = lane & 3;

    const int qm = lane >> 3, rm = lane & 7;
    uint32_t aoff[4];
#pragma unroll
    for (int s = 0; s < 4; s++) {
        int arow = wm + s * 16 + (qm & 1) * 8 + rm;
        aoff[s] = (uint32_t)(arow * ASTR + (qm >> 1) * 4) * 4;
    }
    const uint32_t boff0 = (uint32_t)((wn + (qm >> 1) * 8 + rm) * ASTR + (qm & 1) * 4) * 4;
    const uint32_t boff1 = boff0 + 16 * ASTR * 4;

    uint32_t offL[2], offR[2];
#pragma unroll
    for (int j = 0; j < 2; j++) {
        int row = r0a + 64 * j;
        int b = mt * 128 + row;
        int i1 = a[2 * b], i2 = a[2 * b + 1];
        offL[j] = (uint32_t)(inst * NVOCAB + i1) * (HID * 4);
        offR[j] = (uint32_t)(inst * NVOCAB + i2) * (HID * 4);
    }
    const char* baseL = (const char*)g_HL;
    const char* baseR = (const char*)g_HR;

    float c[4][4][4];
#pragma unroll
    for (int s = 0; s < 4; s++)
#pragma unroll
        for (int q = 0; q < 4; q++)
#pragma unroll
            for (int v = 0; v < 4; v++) c[s][q][v] = 0.f;

    float4 s0[2], s1[2];

#define LDGSUM(KT) do {                                                         \
        const uint32_t kb = (uint32_t)((KT) * 32 + c8) * 4;                     \
        _Pragma("unroll")                                                       \
        for (int j = 0; j < 2; j++) {                                           \
            float4 l0 = *reinterpret_cast<const float4*>(baseL + offL[j] + kb); \
            float4 l1 = *reinterpret_cast<const float4*>(baseL + offL[j] + kb + 16); \
            float4 q0 = *reinterpret_cast<const float4*>(baseR + offR[j] + kb); \
            float4 q1 = *reinterpret_cast<const float4*>(baseR + offR[j] + kb + 16); \
            s0[j] = make_float4(l0.x + q0.x, l0.y + q0.y, l0.z + q0.z, l0.w + q0.w); \
            s1[j] = make_float4(l1.x + q1.x, l1.y + q1.y, l1.z + q1.z, l1.w + q1.w); \
        }                                                                       \
    } while (0)

#define GELUSTS(Ap) do {                                                        \
        _Pragma("unroll")                                                       \
        for (int j = 0; j < 2; j++) {                                           \
            int row = r0a + 64 * j;                                             \
            uint4 u0, u1;                                                       \
            u0.x = f2tf(gelu_poly(s0[j].x));                                    \
            u0.y = f2tf(gelu_poly(s0[j].y));                                    \
            u0.z = f2tf(gelu_poly(s0[j].z));                                    \
            u0.w = f2tf(gelu_poly(s0[j].w));                                    \
            u1.x = f2tf(gelu_poly(s1[j].x));                                    \
            u1.y = f2tf(gelu_poly(s1[j].y));                                    \
            u1.z = f2tf(gelu_poly(s1[j].z));                                    \
            u1.w = f2tf(gelu_poly(s1[j].w));                                    \
            *reinterpret_cast<uint4*>(&(Ap)[row * ASTR + c8]) = u0;             \
            *reinterpret_cast<uint4*>(&(Ap)[row * ASTR + c8 + 4]) = u1;         \
        }                                                                       \
    } while (0)

#define PREFETCH_B2(KT) do {                                                    \
        if ((KT) < NKT) {                                                       \
            const uint32_t bb = bbase + (uint32_t)(((KT) % NSTG2) * (ASZW * 4)); \
            const uint32_t* srcb = Wt + (size_t)(KT) * 32;                      \
            _Pragma("unroll")                                                   \
            for (int j = 0; j < 4; j++) {                                       \
                int cc = t + 256 * j;                                           \
                int row = cc >> 3, kc = (cc & 7) * 4;                           \
                uint32_t dst = bb + (uint32_t)(row * ASTR + kc) * 4;            \
                const uint32_t* src = srcb + (size_t)row * HID + kc;            \
                asm volatile("cp.async.cg.shared.global [%0], [%1], 16;"        \
                             :: "r"(dst), "l"(src) : "memory");                 \
            }                                                                   \
        }                                                                       \
        asm volatile("cp.async.commit_group;" ::: "memory");                    \
    } while (0)

#define COMPUTE_LDSM(abB, bbB)                                                  \
    _Pragma("unroll")                                                           \
    for (int ks = 0; ks < 4; ks++) {                                            \
        const uint32_t kkB = (uint32_t)(ks * 32);                               \
        uint32_t af[4][4], b0[4], b1[4];                                        \
        ldsm4(af[0][0], af[0][1], af[0][2], af[0][3], (abB) + aoff[0] + kkB);   \
        ldsm4(af[1][0], af[1][1], af[1][2], af[1][3], (abB) + aoff[1] + kkB);   \
        ldsm4(af[2][0], af[2][1], af[2][2], af[2][3], (abB) + aoff[2] + kkB);   \
        ldsm4(af[3][0], af[3][1], af[3][2], af[3][3], (abB) + aoff[3] + kkB);   \
        ldsm4(b0[0], b0[1], b0[2], b0[3], (bbB) + boff0 + kkB);                 \
        ldsm4(b1[0], b1[1], b1[2], b1[3], (bbB) + boff1 + kkB);                 \
        _Pragma("unroll")                                                       \
        for (int s = 0; s < 4; s++) {                                           \
            mma8(c[s][0], af[s], &b0[0]);                                       \
            mma8(c[s][1], af[s], &b0[2]);                                       \
            mma8(c[s][2], af[s], &b1[0]);                                       \
            mma8(c[s][3], af[s], &b1[2]);                                       \
        }                                                                       \
    }

    LDGSUM(0);
    GELUSTS(Ab[0]);
    LDGSUM(1);
    PREFETCH_B2(0); PREFETCH_B2(1); PREFETCH_B2(2);

#pragma unroll 1
    for (int kt = 0; kt < NKT; kt++) {
        asm volatile("cp.async.wait_group 2;" ::: "memory");
        __syncthreads();   // B(kt) + A stores visible; compute(kt-1) closed

        PREFETCH_B2(kt + 3);   // reuses slot of B(kt-1), readers done

        const uint32_t abB = abase0 + (uint32_t)((kt & 1) * (ASZW * 4));
        const uint32_t bbB = bbase + (uint32_t)(((kt & 3)) * (ASZW * 4));
        COMPUTE_LDSM(abB, bbB);

        if (kt + 1 < NKT) GELUSTS(Ab[(kt + 1) & 1]);
        if (kt + 2 < NKT) LDGSUM(kt + 2);
    }

    // Epilogue: out shape (BATCH, INST, NVOCAB) fp32
#pragma unroll
    for (int s = 0; s < 4; s++) {
        int rowb = mt * 128 + wm + s * 16 + g;
#pragma unroll
        for (int q = 0; q < 4; q++) {
            int col = wn + q * 8 + 2 * tg;
            *reinterpret_cast<float2*>(out + ((size_t)rowb * INST + inst) * NVOCAB + col) =
                make_float2(c[s][q][0], c[s][q][1]);
            *reinterpret_cast<float2*>(out + ((size_t)(rowb + 8) * INST + inst) * NVOCAB + col) =
                make_float2(c[s][q][2], c[s][q][3]);
        }
    }
}

// ---------------------------------------------------------------------------
extern "C" void kernel_launch(void* const* d_in, const int* in_sizes, int n_in,
                              void* d_out, int out_size)
{
    const int*   a  = (const int*)d_in[0];
    const float* El = (const float*)d_in[1];
    const float* Er = (const float*)d_in[2];
    const float* W1 = (const float*)d_in[3];
    const float* W2 = (const float*)d_in[4];
    float* out = (float*)d_out;

    static int configured = 0;
    if (!configured) {
        cudaFuncSetAttribute(phase1_kernel,
                             cudaFuncAttributeMaxDynamicSharedMemorySize, P1_SMEM);
        cudaFuncSetAttribute(phase2_kernel,
                             cudaFuncAttributeMaxDynamicSharedMemorySize, P2_SMEM);
        configured = 1;
    }

    dim3 g1(HID / 128, INST, 2);
    phase1_kernel<<<g1, 256, P1_SMEM>>>(El, Er, W1, W2);

    dim3 g2(BATCH / 128, INST);
    phase2_kernel<<<g2, 256, P2_SMEM>>>(a, out);
}

// round 15
// speedup vs baseline: 1.5257x; 1.0266x over previous
#include <cuda_runtime.h>
#include <cuda_bf16.h>
#include <cstdint>
#include <math.h>

#define INST   64
#define NVOCAB 128
#define ED     256
#define HID    1024
#define BATCH  2048

// Precomputed HL[i] = E_l[i] @ W1[i], HR[i] = E_r[i] @ W1[i]  (fp32 scratch)
__device__ float g_HL[INST * NVOCAB * HID];
__device__ float g_HR[INST * NVOCAB * HID];
// W2 transposed + tf32: [inst][n][k]  (filled by phase1 tail)
__device__ uint32_t g_W2t[INST * NVOCAB * HID];

__device__ __forceinline__ uint32_t f2tf(float f) {
    uint32_t u;
    asm("cvt.rna.tf32.f32 %0, %1;" : "=r"(u) : "f"(f));
    return u;
}
__device__ __forceinline__ void mma8(float* c, const uint32_t* a, const uint32_t* b) {
    asm volatile(
        "mma.sync.aligned.m16n8k8.row.col.f32.tf32.tf32.f32 "
        "{%0,%1,%2,%3}, {%4,%5,%6,%7}, {%8,%9}, {%0,%1,%2,%3};"
        : "+f"(c[0]), "+f"(c[1]), "+f"(c[2]), "+f"(c[3])
        : "r"(a[0]), "r"(a[1]), "r"(a[2]), "r"(a[3]), "r"(b[0]), "r"(b[1]));
}
__device__ __forceinline__ void ldsm4(uint32_t& r0, uint32_t& r1, uint32_t& r2,
                                      uint32_t& r3, uint32_t addr) {
    asm volatile("ldmatrix.sync.aligned.m8n8.x4.shared.b16 {%0,%1,%2,%3}, [%4];"
                 : "=r"(r0), "=r"(r1), "=r"(r2), "=r"(r3) : "r"(addr));
}
__device__ __forceinline__ uint32_t smem_u32(const void* p) {
    uint32_t a;
    asm("{ .reg .u64 t; cvta.to.shared.u64 t, %1; cvt.u32.u64 %0, t; }" : "=r"(a) : "l"(p));
    return a;
}

// gelu via erf(x/sqrt2) = x*Q(x^2), 8-term Taylor (validated R10+).
__device__ __forceinline__ float gelu_poly(float x) {
    float t = x * x;
    float p = fmaf(t, -8.24550e-8f, 1.331920e-6f);
    p = fmaf(t, p, -1.888910e-5f);
    p = fmaf(t, p, 2.308700e-4f);
    p = fmaf(t, p, -2.3746565e-3f);
    p = fmaf(t, p, 1.9947114e-2f);
    p = fmaf(t, p, -0.13298076f);
    p = fmaf(t, p, 0.79788456f);
    float e  = x * p;
    float hx = 0.5f * x;
    return fmaf(hx, e, hx);
}

// Strides (words).
#define ASTR 36
#define BSTR 136
#define ASZW (128 * ASTR)     // 4608 words = 18432 B
#define BSZW (32 * BSTR)      // 4352 words
#define NKT  (HID / 32)       // 32 k-tiles in phase 2
#define NKT1 (ED / 32)        // 8 k-tiles in phase 1
#define NSTG2 4
#define P1_SMEM ((ASZW + 2 * BSZW) * 4)               // 53248 B (A dbl-buf shares ASZW? no: see below)
#undef  P1_SMEM
#define P1_SMEM ((2 * ASZW + 2 * BSZW) * 4)           // 71680 B -> 2 CTAs/SM
#define P2_SMEM ((2 + NSTG2) * ASZW * 4)              // 110592 B

// ---------------------------------------------------------------------------
// Phase 1: HL/HR[i] = E[i] (128x256) @ W1[i] (256x1024)
// Produce-ahead pipeline (phase2 pattern): A(E) and B(W1) register-staged one
// iter ahead, cvt at produce, double-buffered tiles, ONE sync per k-tile.
// 8-warp 64x32 tiles. grid (8, 64, 2), 256 threads, 2 CTAs/SM.
// Tail: transpose + tf32 W2 into g_W2t.
// ---------------------------------------------------------------------------
__global__ __launch_bounds__(256, 2) void phase1_kernel(
    const float* __restrict__ El, const float* __restrict__ Er,
    const float* __restrict__ W1, const float* __restrict__ W2)
{
    extern __shared__ uint32_t dsm[];
    uint32_t* Ab[2] = { dsm, dsm + ASZW };
    uint32_t* Bb[2] = { dsm + 2 * ASZW, dsm + 2 * ASZW + BSZW };

    const int nt = blockIdx.x, inst = blockIdx.y, side = blockIdx.z;
    const float* E   = (side ? Er : El) + inst * NVOCAB * ED;
    float*       Hst = (side ? g_HR : g_HL) + inst * NVOCAB * HID + nt * 128;
    const float* W   = W1 + inst * ED * HID + nt * 128;

    const int t    = threadIdx.x;
    const int lane = t & 31, w = t >> 5;
    const int wm = (w & 1) * 64, wn = (w >> 1) * 32;
    const int g = lane >> 2, tg = lane & 3;
    const int r0a = t >> 2, c8 = (t & 3) * 8;   // A producer: rows r0a, r0a+64
    const int kB = t >> 5, ncB = (t & 31) * 4;  // B producer base (4 k-rows apart)

    float c[4][4][4];
#pragma unroll
    for (int s = 0; s < 4; s++)
#pragma unroll
        for (int q = 0; q < 4; q++)
#pragma unroll
            for (int v = 0; v < 4; v++) c[s][q][v] = 0.f;

    // Register staging: A = 2 rows x 8 floats, B = 4 x float4.
    float4 sa[4];   // sa[0..1]=row r0a (c8, c8+4), sa[2..3]=row r0a+64
    float4 sb[4];

#define P1_LDG(KT) do {                                                         \
        const int k0 = (KT) * 32;                                               \
        sa[0] = *reinterpret_cast<const float4*>(E + r0a * ED + k0 + c8);       \
        sa[1] = *reinterpret_cast<const float4*>(E + r0a * ED + k0 + c8 + 4);   \
        sa[2] = *reinterpret_cast<const float4*>(E + (r0a + 64) * ED + k0 + c8); \
        sa[3] = *reinterpret_cast<const float4*>(E + (r0a + 64) * ED + k0 + c8 + 4); \
        _Pragma("unroll")                                                       \
        for (int j = 0; j < 4; j++)                                             \
            sb[j] = *reinterpret_cast<const float4*>(                           \
                W + (size_t)(k0 + kB + 8 * j) * HID + ncB);                     \
    } while (0)

#define P1_STS(AB) do {                                                         \
        uint32_t* Ap = Ab[(AB)];                                                \
        uint32_t* Bp = Bb[(AB)];                                                \
        *reinterpret_cast<uint4*>(&Ap[r0a * ASTR + c8]) =                       \
            make_uint4(f2tf(sa[0].x), f2tf(sa[0].y), f2tf(sa[0].z), f2tf(sa[0].w)); \
        *reinterpret_cast<uint4*>(&Ap[r0a * ASTR + c8 + 4]) =                   \
            make_uint4(f2tf(sa[1].x), f2tf(sa[1].y), f2tf(sa[1].z), f2tf(sa[1].w)); \
        *reinterpret_cast<uint4*>(&Ap[(r0a + 64) * ASTR + c8]) =                \
            make_uint4(f2tf(sa[2].x), f2tf(sa[2].y), f2tf(sa[2].z), f2tf(sa[2].w)); \
        *reinterpret_cast<uint4*>(&Ap[(r0a + 64) * ASTR + c8 + 4]) =            \
            make_uint4(f2tf(sa[3].x), f2tf(sa[3].y), f2tf(sa[3].z), f2tf(sa[3].w)); \
        _Pragma("unroll")                                                       \
        for (int j = 0; j < 4; j++)                                             \
            *reinterpret_cast<uint4*>(&Bp[(kB + 8 * j) * BSTR + ncB]) =         \
                make_uint4(f2tf(sb[j].x), f2tf(sb[j].y), f2tf(sb[j].z), f2tf(sb[j].w)); \
    } while (0)

    // Prologue: tile 0 into buf0; tile 1 staged in regs.
    P1_LDG(0);
    P1_STS(0);
    P1_LDG(1);

#pragma unroll 1
    for (int kt = 0; kt < NKT1; kt++) {
        __syncthreads();   // A/B(kt) visible; all reads of buf (kt+1)&1 closed

        // Compute on buffer kt&1 (scalar-LDS fragment path, known-good banks)
        const uint32_t* Ap = Ab[kt & 1];
        const uint32_t* Bp = Bb[kt & 1];
#pragma unroll
        for (int ks = 0; ks < 4; ks++) {
            const int kk = ks * 8;
            uint32_t af[4][4];
#pragma unroll
            for (int s = 0; s < 4; s++) {
                int r0 = wm + s * 16 + g;
                af[s][0] = Ap[r0 * ASTR + kk + tg];
                af[s][1] = Ap[(r0 + 8) * ASTR + kk + tg];
                af[s][2] = Ap[r0 * ASTR + kk + 4 + tg];
                af[s][3] = Ap[(r0 + 8) * ASTR + kk + 4 + tg];
            }
            uint32_t bf[4][2];
#pragma unroll
            for (int q = 0; q < 4; q++) {
                int nb = wn + q * 8 + g;
                bf[q][0] = Bp[(kk + tg) * BSTR + nb];
                bf[q][1] = Bp[(kk + 4 + tg) * BSTR + nb];
            }
#pragma unroll
            for (int s = 0; s < 4; s++)
#pragma unroll
                for (int q = 0; q < 4; q++)
                    mma8(c[s][q], af[s], bf[q]);
        }

        if (kt + 1 < NKT1) P1_STS((kt + 1) & 1);  // staged last iter
        if (kt + 2 < NKT1) P1_LDG(kt + 2);        // hides under next compute
    }

#pragma unroll
    for (int s = 0; s < 4; s++) {
        int row = wm + s * 16 + g;
#pragma unroll
        for (int q = 0; q < 4; q++) {
            int col = wn + q * 8 + 2 * tg;
            *reinterpret_cast<float2*>(Hst + row * HID + col) =
                make_float2(c[s][q][0], c[s][q][1]);
            *reinterpret_cast<float2*>(Hst + (row + 8) * HID + col) =
                make_float2(c[s][q][2], c[s][q][3]);
        }
    }

    // Tail: transpose + tf32 W2 [i][k][n] -> g_W2t [i][n][k], 8 tiles/CTA.
    {
        float* tsm = reinterpret_cast<float*>(dsm);   // 32x33 tile
        const int ci = ((blockIdx.z * INST + blockIdx.y) * (HID / 128)
                        + blockIdx.x);                 // 0..1023
        const int ty = t >> 5, tx = t & 31;
#pragma unroll 1
        for (int j = 0; j < 8; j++) {
            const int tt = ci * 8 + j;                 // 0..8191
            const int i  = tt >> 7;
            const int rem = tt & 127;
            const int kt32 = rem >> 2, nt32 = rem & 3;
            __syncthreads();
#pragma unroll
            for (int jj = 0; jj < 4; jj++) {
                int kk = ty + 8 * jj;
                tsm[kk * 33 + tx] =
                    W2[((size_t)i * HID + kt32 * 32 + kk) * NVOCAB + nt32 * 32 + tx];
            }
            __syncthreads();
#pragma unroll
            for (int jj = 0; jj < 4; jj++) {
                int nn = ty + 8 * jj;
                g_W2t[((size_t)i * NVOCAB + nt32 * 32 + nn) * HID + kt32 * 32 + tx] =
                    f2tf(tsm[tx * 33 + nn]);
            }
        }
    }
}

// ---------------------------------------------------------------------------
// Phase 2 (byte-exact R10 config, best measured 272.6us):
// ldmatrix fragment loads (A row-major, B n-major), 8-term poly gelu,
// produce-ahead pipeline, B depth 4. grid (16, 64), 256 threads, 2 CTAs/SM.
// ---------------------------------------------------------------------------
__global__ __launch_bounds__(256, 2) void phase2_kernel(
    const int* __restrict__ a, float* __restrict__ out)
{
    extern __shared__ uint32_t dsm[];
    uint32_t* Ab[2] = { dsm, dsm + ASZW };
    const uint32_t abase0 = smem_u32(dsm);
    const uint32_t bbase  = abase0 + 2 * ASZW * 4;

    const int mt = blockIdx.x, inst = blockIdx.y;
    const uint32_t* Wt = g_W2t + (size_t)inst * NVOCAB * HID;  // [n][k]

    const int t    = threadIdx.x;
    const int lane = t & 31, w = t >> 5;
    const int wm = (w & 1) * 64, wn = (w >> 1) * 32;
    const int r0a = t >> 2, c8 = (t & 3) * 8;
    const int g = lane >> 2, tg = lane & 3;

    const int qm = lane >> 3, rm = lane & 7;
    uint32_t aoff[4];
#pragma unroll
    for (int s = 0; s < 4; s++) {
        int arow = wm + s * 16 + (qm & 1) * 8 + rm;
        aoff[s] = (uint32_t)(arow * ASTR + (qm >> 1) * 4) * 4;
    }
    const uint32_t boff0 = (uint32_t)((wn + (qm >> 1) * 8 + rm) * ASTR + (qm & 1) * 4) * 4;
    const uint32_t boff1 = boff0 + 16 * ASTR * 4;

    uint32_t offL[2], offR[2];
#pragma unroll
    for (int j = 0; j < 2; j++) {
        int row = r0a + 64 * j;
        int b = mt * 128 + row;
        int i1 = a[2 * b], i2 = a[2 * b + 1];
        offL[j] = (uint32_t)(inst * NVOCAB + i1) * (HID * 4);
        offR[j] = (uint32_t)(inst * NVOCAB + i2) * (HID * 4);
    }
    const char* baseL = (const char*)g_HL;
    const char* baseR = (const char*)g_HR;

    float c[4][4][4];
#pragma unroll
    for (int s = 0; s < 4; s++)
#pragma unroll
        for (int q = 0; q < 4; q++)
#pragma unroll
            for (int v = 0; v < 4; v++) c[s][q][v] = 0.f;

    float4 s0[2], s1[2];

#define LDGSUM(KT) do {                                                         \
        const uint32_t kb = (uint32_t)((KT) * 32 + c8) * 4;                     \
        _Pragma("unroll")                                                       \
        for (int j = 0; j < 2; j++) {                                           \
            float4 l0 = *reinterpret_cast<const float4*>(baseL + offL[j] + kb); \
            float4 l1 = *reinterpret_cast<const float4*>(baseL + offL[j] + kb + 16); \
            float4 q0 = *reinterpret_cast<const float4*>(baseR + offR[j] + kb); \
            float4 q1 = *reinterpret_cast<const float4*>(baseR + offR[j] + kb + 16); \
            s0[j] = make_float4(l0.x + q0.x, l0.y + q0.y, l0.z + q0.z, l0.w + q0.w); \
            s1[j] = make_float4(l1.x + q1.x, l1.y + q1.y, l1.z + q1.z, l1.w + q1.w); \
        }                                                                       \
    } while (0)

#define GELUSTS(Ap) do {                                                        \
        _Pragma("unroll")                                                       \
        for (int j = 0; j < 2; j++) {                                           \
            int row = r0a + 64 * j;                                             \
            uint4 u0, u1;                                                       \
            u0.x = f2tf(gelu_poly(s0[j].x));                                    \
            u0.y = f2tf(gelu_poly(s0[j].y));                                    \
            u0.z = f2tf(gelu_poly(s0[j].z));                                    \
            u0.w = f2tf(gelu_poly(s0[j].w));                                    \
            u1.x = f2tf(gelu_poly(s1[j].x));                                    \
            u1.y = f2tf(gelu_poly(s1[j].y));                                    \
            u1.z = f2tf(gelu_poly(s1[j].z));                                    \
            u1.w = f2tf(gelu_poly(s1[j].w));                                    \
            *reinterpret_cast<uint4*>(&(Ap)[row * ASTR + c8]) = u0;             \
            *reinterpret_cast<uint4*>(&(Ap)[row * ASTR + c8 + 4]) = u1;         \
        }                                                                       \
    } while (0)

#define PREFETCH_B2(KT) do {                                                    \
        if ((KT) < NKT) {                                                       \
            const uint32_t bb = bbase + (uint32_t)(((KT) % NSTG2) * (ASZW * 4)); \
            const uint32_t* srcb = Wt + (size_t)(KT) * 32;                      \
            _Pragma("unroll")                                                   \
            for (int j = 0; j < 4; j++) {                                       \
                int cc = t + 256 * j;                                           \
                int row = cc >> 3, kc = (cc & 7) * 4;                           \
                uint32_t dst = bb + (uint32_t)(row * ASTR + kc) * 4;            \
                const uint32_t* src = srcb + (size_t)row * HID + kc;            \
                asm volatile("cp.async.cg.shared.global [%0], [%1], 16;"        \
                             :: "r"(dst), "l"(src) : "memory");                 \
            }                                                                   \
        }                                                                       \
        asm volatile("cp.async.commit_group;" ::: "memory");                    \
    } while (0)

#define COMPUTE_LDSM(abB, bbB)                                                  \
    _Pragma("unroll")                                                           \
    for (int ks = 0; ks < 4; ks++) {                                            \
        const uint32_t kkB = (uint32_t)(ks * 32);                               \
        uint32_t af[4][4], b0[4], b1[4];                                        \
        ldsm4(af[0][0], af[0][1], af[0][2], af[0][3], (abB) + aoff[0] + kkB);   \
        ldsm4(af[1][0], af[1][1], af[1][2], af[1][3], (abB) + aoff[1] + kkB);   \
        ldsm4(af[2][0], af[2][1], af[2][2], af[2][3], (abB) + aoff[2] + kkB);   \
        ldsm4(af[3][0], af[3][1], af[3][2], af[3][3], (abB) + aoff[3] + kkB);   \
        ldsm4(b0[0], b0[1], b0[2], b0[3], (bbB) + boff0 + kkB);                 \
        ldsm4(b1[0], b1[1], b1[2], b1[3], (bbB) + boff1 + kkB);                 \
        _Pragma("unroll")                                                       \
        for (int s = 0; s < 4; s++) {                                           \
            mma8(c[s][0], af[s], &b0[0]);                                       \
            mma8(c[s][1], af[s], &b0[2]);                                       \
            mma8(c[s][2], af[s], &b1[0]);                                       \
            mma8(c[s][3], af[s], &b1[2]);                                       \
        }                                                                       \
    }

    LDGSUM(0);
    GELUSTS(Ab[0]);
    LDGSUM(1);
    PREFETCH_B2(0); PREFETCH_B2(1); PREFETCH_B2(2);

#pragma unroll 1
    for (int kt = 0; kt < NKT; kt++) {
        asm volatile("cp.async.wait_group 2;" ::: "memory");
        __syncthreads();   // B(kt) + A stores visible; compute(kt-1) closed

        PREFETCH_B2(kt + 3);   // reuses slot of B(kt-1), readers done

        const uint32_t abB = abase0 + (uint32_t)((kt & 1) * (ASZW * 4));
        const uint32_t bbB = bbase + (uint32_t)(((kt & 3)) * (ASZW * 4));
        COMPUTE_LDSM(abB, bbB);

        if (kt + 1 < NKT) GELUSTS(Ab[(kt + 1) & 1]);
        if (kt + 2 < NKT) LDGSUM(kt + 2);
    }

    // Epilogue: out shape (BATCH, INST, NVOCAB) fp32
#pragma unroll
    for (int s = 0; s < 4; s++) {
        int rowb = mt * 128 + wm + s * 16 + g;
#pragma unroll
        for (int q = 0; q < 4; q++) {
            int col = wn + q * 8 + 2 * tg;
            *reinterpret_cast<float2*>(out + ((size_t)rowb * INST + inst) * NVOCAB + col) =
                make_float2(c[s][q][0], c[s][q][1]);
            *reinterpret_cast<float2*>(out + ((size_t)(rowb + 8) * INST + inst) * NVOCAB + col) =
                make_float2(c[s][q][2], c[s][q][3]);
        }
    }
}

// ---------------------------------------------------------------------------
extern "C" void kernel_launch(void* const* d_in, const int* in_sizes, int n_in,
                              void* d_out, int out_size)
{
    const int*   a  = (const int*)d_in[0];
    const float* El = (const float*)d_in[1];
    const float* Er = (const float*)d_in[2];
    const float* W1 = (const float*)d_in[3];
    const float* W2 = (const float*)d_in[4];
    float* out = (float*)d_out;

    static int configured = 0;
    if (!configured) {
        cudaFuncSetAttribute(phase1_kernel,
                             cudaFuncAttributeMaxDynamicSharedMemorySize, P1_SMEM);
        cudaFuncSetAttribute(phase2_kernel,
                             cudaFuncAttributeMaxDynamicSharedMemorySize, P2_SMEM);
        configured = 1;
    }

    dim3 g1(HID / 128, INST, 2);
    phase1_kernel<<<g1, 256, P1_SMEM>>>(El, Er, W1, W2);

    dim3 g2(BATCH / 128, INST);
    phase2_kernel<<<g2, 256, P2_SMEM>>>(a, out);
}

// round 17
// speedup vs baseline: 1.8763x; 1.2298x over previous
#include <cuda_runtime.h>
#include <cuda_bf16.h>
#include <cuda_fp16.h>
#include <cstdint>
#include <math.h>

#define INST   64
#define NVOCAB 128
#define ED     256
#define HID    1024
#define BATCH  2048

// Precomputed HL[i] = E_l[i] @ W1[i], HR[i] = E_r[i] @ W1[i]  (fp32 scratch)
__device__ float g_HL[INST * NVOCAB * HID];
__device__ float g_HR[INST * NVOCAB * HID];
// W2 transposed + fp16: [inst][n][k]  (filled by phase1 tail)
__device__ __half g_W2h[INST * NVOCAB * HID];

__device__ __forceinline__ uint32_t f2tf(float f) {
    uint32_t u;
    asm("cvt.rna.tf32.f32 %0, %1;" : "=r"(u) : "f"(f));
    return u;
}
// pack two fp32 -> f16x2 (lo = first arg, hi = second)
__device__ __forceinline__ uint32_t pack_h2(float lo, float hi) {
    uint32_t r;
    asm("cvt.rn.f16x2.f32 %0, %1, %2;" : "=r"(r) : "f"(hi), "f"(lo));
    return r;
}
__device__ __forceinline__ void mma8(float* c, const uint32_t* a, const uint32_t* b) {
    asm volatile(
        "mma.sync.aligned.m16n8k8.row.col.f32.tf32.tf32.f32 "
        "{%0,%1,%2,%3}, {%4,%5,%6,%7}, {%8,%9}, {%0,%1,%2,%3};"
        : "+f"(c[0]), "+f"(c[1]), "+f"(c[2]), "+f"(c[3])
        : "r"(a[0]), "r"(a[1]), "r"(a[2]), "r"(a[3]), "r"(b[0]), "r"(b[1]));
}
__device__ __forceinline__ void mma16(float* c, const uint32_t* a, const uint32_t* b) {
    asm volatile(
        "mma.sync.aligned.m16n8k16.row.col.f32.f16.f16.f32 "
        "{%0,%1,%2,%3}, {%4,%5,%6,%7}, {%8,%9}, {%0,%1,%2,%3};"
        : "+f"(c[0]), "+f"(c[1]), "+f"(c[2]), "+f"(c[3])
        : "r"(a[0]), "r"(a[1]), "r"(a[2]), "r"(a[3]), "r"(b[0]), "r"(b[1]));
}
__device__ __forceinline__ void ldsm4(uint32_t& r0, uint32_t& r1, uint32_t& r2,
                                      uint32_t& r3, uint32_t addr) {
    asm volatile("ldmatrix.sync.aligned.m8n8.x4.shared.b16 {%0,%1,%2,%3}, [%4];"
                 : "=r"(r0), "=r"(r1), "=r"(r2), "=r"(r3) : "r"(addr));
}
__device__ __forceinline__ uint32_t smem_u32(const void* p) {
    uint32_t a;
    asm("{ .reg .u64 t; cvta.to.shared.u64 t, %1; cvt.u32.u64 %0, t; }" : "=r"(a) : "l"(p));
    return a;
}

// gelu via erf(x/sqrt2) = x*Q(x^2), 8-term Taylor (validated R10+).
__device__ __forceinline__ float gelu_poly(float x) {
    float t = x * x;
    float p = fmaf(t, -8.24550e-8f, 1.331920e-6f);
    p = fmaf(t, p, -1.888910e-5f);
    p = fmaf(t, p, 2.308700e-4f);
    p = fmaf(t, p, -2.3746565e-3f);
    p = fmaf(t, p, 1.9947114e-2f);
    p = fmaf(t, p, -0.13298076f);
    p = fmaf(t, p, 0.79788456f);
    float e  = x * p;
    float hx = 0.5f * x;
    return fmaf(hx, e, hx);
}

// Strides.
#define ASTR 36               // phase1 word stride
#define BSTR 136
#define ASZW (128 * ASTR)
#define BSZW (32 * BSTR)
#define NKT  (HID / 32)       // 32 k-tiles in phase 2
#define NKT1 (ED / 32)
#define NSTG2 4
#define P1_SMEM ((2 * ASZW + 2 * BSZW) * 4)           // 71680 B -> 2 CTAs/SM
// Phase 2 fp16 tiles: 128 rows x 32 fp16 (64 B used), row stride 80 B:
// 16-byte aligned per row AND conflict-free ldmatrix phases (banks 20r+c).
#define RSTRB 80
#define AT2B  (128 * RSTRB)   // 10240 B per tile
#define P2_SMEM ((2 + NSTG2) * AT2B)                  // 61440 B -> 2 CTAs/SM

// ---------------------------------------------------------------------------
// Phase 1 (R14 pipelined, known good): tf32 64x32 tiles, produce-ahead,
// ONE sync per tile. Tail: transpose + fp16 W2 into g_W2h.
// ---------------------------------------------------------------------------
__global__ __launch_bounds__(256, 2) void phase1_kernel(
    const float* __restrict__ El, const float* __restrict__ Er,
    const float* __restrict__ W1, const float* __restrict__ W2)
{
    extern __shared__ uint32_t dsm[];
    uint32_t* Ab[2] = { dsm, dsm + ASZW };
    uint32_t* Bb[2] = { dsm + 2 * ASZW, dsm + 2 * ASZW + BSZW };

    const int nt = blockIdx.x, inst = blockIdx.y, side = blockIdx.z;
    const float* E   = (side ? Er : El) + inst * NVOCAB * ED;
    float*       Hst = (side ? g_HR : g_HL) + inst * NVOCAB * HID + nt * 128;
    const float* W   = W1 + inst * ED * HID + nt * 128;

    const int t    = threadIdx.x;
    const int lane = t & 31, w = t >> 5;
    const int wm = (w & 1) * 64, wn = (w >> 1) * 32;
    const int g = lane >> 2, tg = lane & 3;
    const int r0a = t >> 2, c8 = (t & 3) * 8;
    const int kB = t >> 5, ncB = (t & 31) * 4;

    float c[4][4][4];
#pragma unroll
    for (int s = 0; s < 4; s++)
#pragma unroll
        for (int q = 0; q < 4; q++)
#pragma unroll
            for (int v = 0; v < 4; v++) c[s][q][v] = 0.f;

    float4 sa[4], sb[4];

#define P1_LDG(KT) do {                                                         \
        const int k0 = (KT) * 32;                                               \
        sa[0] = *reinterpret_cast<const float4*>(E + r0a * ED + k0 + c8);       \
        sa[1] = *reinterpret_cast<const float4*>(E + r0a * ED + k0 + c8 + 4);   \
        sa[2] = *reinterpret_cast<const float4*>(E + (r0a + 64) * ED + k0 + c8); \
        sa[3] = *reinterpret_cast<const float4*>(E + (r0a + 64) * ED + k0 + c8 + 4); \
        _Pragma("unroll")                                                       \
        for (int j = 0; j < 4; j++)                                             \
            sb[j] = *reinterpret_cast<const float4*>(                           \
                W + (size_t)(k0 + kB + 8 * j) * HID + ncB);                     \
    } while (0)

#define P1_STS(AB) do {                                                         \
        uint32_t* Ap = Ab[(AB)];                                                \
        uint32_t* Bp = Bb[(AB)];                                                \
        *reinterpret_cast<uint4*>(&Ap[r0a * ASTR + c8]) =                       \
            make_uint4(f2tf(sa[0].x), f2tf(sa[0].y), f2tf(sa[0].z), f2tf(sa[0].w)); \
        *reinterpret_cast<uint4*>(&Ap[r0a * ASTR + c8 + 4]) =                   \
            make_uint4(f2tf(sa[1].x), f2tf(sa[1].y), f2tf(sa[1].z), f2tf(sa[1].w)); \
        *reinterpret_cast<uint4*>(&Ap[(r0a + 64) * ASTR + c8]) =                \
            make_uint4(f2tf(sa[2].x), f2tf(sa[2].y), f2tf(sa[2].z), f2tf(sa[2].w)); \
        *reinterpret_cast<uint4*>(&Ap[(r0a + 64) * ASTR + c8 + 4]) =            \
            make_uint4(f2tf(sa[3].x), f2tf(sa[3].y), f2tf(sa[3].z), f2tf(sa[3].w)); \
        _Pragma("unroll")                                                       \
        for (int j = 0; j < 4; j++)                                             \
            *reinterpret_cast<uint4*>(&Bp[(kB + 8 * j) * BSTR + ncB]) =         \
                make_uint4(f2tf(sb[j].x), f2tf(sb[j].y), f2tf(sb[j].z), f2tf(sb[j].w)); \
    } while (0)

    P1_LDG(0);
    P1_STS(0);
    P1_LDG(1);

#pragma unroll 1
    for (int kt = 0; kt < NKT1; kt++) {
        __syncthreads();

        const uint32_t* Ap = Ab[kt & 1];
        const uint32_t* Bp = Bb[kt & 1];
#pragma unroll
        for (int ks = 0; ks < 4; ks++) {
            const int kk = ks * 8;
            uint32_t af[4][4];
#pragma unroll
            for (int s = 0; s < 4; s++) {
                int r0 = wm + s * 16 + g;
                af[s][0] = Ap[r0 * ASTR + kk + tg];
                af[s][1] = Ap[(r0 + 8) * ASTR + kk + tg];
                af[s][2] = Ap[r0 * ASTR + kk + 4 + tg];
                af[s][3] = Ap[(r0 + 8) * ASTR + kk + 4 + tg];
            }
            uint32_t bf[4][2];
#pragma unroll
            for (int q = 0; q < 4; q++) {
                int nb = wn + q * 8 + g;
                bf[q][0] = Bp[(kk + tg) * BSTR + nb];
                bf[q][1] = Bp[(kk + 4 + tg) * BSTR + nb];
            }
#pragma unroll
            for (int s = 0; s < 4; s++)
#pragma unroll
                for (int q = 0; q < 4; q++)
                    mma8(c[s][q], af[s], bf[q]);
        }

        if (kt + 1 < NKT1) P1_STS((kt + 1) & 1);
        if (kt + 2 < NKT1) P1_LDG(kt + 2);
    }

#pragma unroll
    for (int s = 0; s < 4; s++) {
        int row = wm + s * 16 + g;
#pragma unroll
        for (int q = 0; q < 4; q++) {
            int col = wn + q * 8 + 2 * tg;
            *reinterpret_cast<float2*>(Hst + row * HID + col) =
                make_float2(c[s][q][0], c[s][q][1]);
            *reinterpret_cast<float2*>(Hst + (row + 8) * HID + col) =
                make_float2(c[s][q][2], c[s][q][3]);
        }
    }

    // Tail: transpose + fp16 W2 [i][k][n] -> g_W2h [i][n][k], 8 tiles/CTA.
    {
        float* tsm = reinterpret_cast<float*>(dsm);   // 32x33 tile
        const int ci = ((blockIdx.z * INST + blockIdx.y) * (HID / 128)
                        + blockIdx.x);                 // 0..1023
        const int ty = t >> 5, tx = t & 31;
#pragma unroll 1
        for (int j = 0; j < 8; j++) {
            const int tt = ci * 8 + j;                 // 0..8191
            const int i  = tt >> 7;
            const int rem = tt & 127;
            const int kt32 = rem >> 2, nt32 = rem & 3;
            __syncthreads();
#pragma unroll
            for (int jj = 0; jj < 4; jj++) {
                int kk = ty + 8 * jj;
                tsm[kk * 33 + tx] =
                    W2[((size_t)i * HID + kt32 * 32 + kk) * NVOCAB + nt32 * 32 + tx];
            }
            __syncthreads();
#pragma unroll
            for (int jj = 0; jj < 4; jj++) {
                int nn = ty + 8 * jj;
                g_W2h[((size_t)i * NVOCAB + nt32 * 32 + nn) * HID + kt32 * 32 + tx] =
                    __float2half_rn(tsm[tx * 33 + nn]);
            }
        }
    }
}

// ---------------------------------------------------------------------------
// Phase 2: fp16 m16n8k16 MMA. A = gelu(gather) packed f16x2 on the fly;
// B = pre-converted fp16 W2 [n][k] via cp.async, 4-stage ring.
// grid (16, 64), 256 threads, 2 CTAs/SM.
// ---------------------------------------------------------------------------
__global__ __launch_bounds__(256, 2) void phase2_kernel(
    const int* __restrict__ a, float* __restrict__ out)
{
    extern __shared__ uint32_t dsm[];
    const uint32_t abase0 = smem_u32(dsm);
    const uint32_t bbase  = abase0 + 2 * AT2B;

    const int mt = blockIdx.x, inst = blockIdx.y;
    const __half* Wt = g_W2h + (size_t)inst * NVOCAB * HID;  // [n][k]

    const int t    = threadIdx.x;
    const int lane = t & 31, w = t >> 5;
    const int wm = (w & 1) * 64, wn = (w >> 1) * 32;
    const int r0a = t >> 2, c8 = (t & 3) * 8;
    const int g = lane >> 2, tg = lane & 3;

    // ldmatrix b16 per-lane offsets (bytes within a tile, row stride 80 B)
    const int qm = lane >> 3, rm = lane & 7;
    uint32_t aoff[4];
#pragma unroll
    for (int s = 0; s < 4; s++) {
        int arow = wm + s * 16 + (qm & 1) * 8 + rm;
        aoff[s] = (uint32_t)(arow * RSTRB) + (uint32_t)((qm >> 1) * 16);
    }
    const uint32_t boff0 = (uint32_t)((wn + (qm >> 1) * 8 + rm) * RSTRB)
                         + (uint32_t)((qm & 1) * 16);
    const uint32_t boff1 = boff0 + 16 * RSTRB;

    uint32_t offL[2], offR[2];
#pragma unroll
    for (int j = 0; j < 2; j++) {
        int row = r0a + 64 * j;
        int b = mt * 128 + row;
        int i1 = a[2 * b], i2 = a[2 * b + 1];
        offL[j] = (uint32_t)(inst * NVOCAB + i1) * (HID * 4);
        offR[j] = (uint32_t)(inst * NVOCAB + i2) * (HID * 4);
    }
    const char* baseL = (const char*)g_HL;
    const char* baseR = (const char*)g_HR;

    float c[4][4][4];
#pragma unroll
    for (int s = 0; s < 4; s++)
#pragma unroll
        for (int q = 0; q < 4; q++)
#pragma unroll
            for (int v = 0; v < 4; v++) c[s][q][v] = 0.f;

    float4 s0[2], s1[2];

#define LDGSUM(KT) do {                                                         \
        const uint32_t kb = (uint32_t)((KT) * 32 + c8) * 4;                     \
        _Pragma("unroll")                                                       \
        for (int j = 0; j < 2; j++) {                                           \
            float4 l0 = *reinterpret_cast<const float4*>(baseL + offL[j] + kb); \
            float4 l1 = *reinterpret_cast<const float4*>(baseL + offL[j] + kb + 16); \
            float4 q0 = *reinterpret_cast<const float4*>(baseR + offR[j] + kb); \
            float4 q1 = *reinterpret_cast<const float4*>(baseR + offR[j] + kb + 16); \
            s0[j] = make_float4(l0.x + q0.x, l0.y + q0.y, l0.z + q0.z, l0.w + q0.w); \
            s1[j] = make_float4(l1.x + q1.x, l1.y + q1.y, l1.z + q1.z, l1.w + q1.w); \
        }                                                                       \
    } while (0)

    // gelu + pack 8 values -> one uint4 of f16x2 per row (16B-aligned: 80|16).
#define GELUSTS(ApB) do {                                                       \
        _Pragma("unroll")                                                       \
        for (int j = 0; j < 2; j++) {                                           \
            int row = r0a + 64 * j;                                             \
            uint4 u;                                                            \
            u.x = pack_h2(gelu_poly(s0[j].x), gelu_poly(s0[j].y));              \
            u.y = pack_h2(gelu_poly(s0[j].z), gelu_poly(s0[j].w));              \
            u.z = pack_h2(gelu_poly(s1[j].x), gelu_poly(s1[j].y));              \
            u.w = pack_h2(gelu_poly(s1[j].z), gelu_poly(s1[j].w));              \
            *reinterpret_cast<uint4*>((char*)dsm + (ApB) + row * RSTRB          \
                                      + (t & 3) * 16) = u;                      \
        }                                                                       \
    } while (0)

    // B prefetch: 128 n-rows x 64 B = 512 x 16B chunks / 256 thr = 2 each.
#define PREFETCH_B2(KT) do {                                                    \
        if ((KT) < NKT) {                                                       \
            const uint32_t bb = bbase + (uint32_t)(((KT) % NSTG2) * AT2B);      \
            const __half* srcb = Wt + (size_t)(KT) * 32;                        \
            _Pragma("unroll")                                                   \
            for (int j = 0; j < 2; j++) {                                       \
                int cc = t + 256 * j;                                           \
                int row = cc >> 2, kc = cc & 3;                                 \
                uint32_t dst = bb + (uint32_t)(row * RSTRB + kc * 16);          \
                const __half* src = srcb + (size_t)row * HID + kc * 8;          \
                asm volatile("cp.async.cg.shared.global [%0], [%1], 16;"        \
                             :: "r"(dst), "l"(src) : "memory");                 \
            }                                                                   \
        }                                                                       \
        asm volatile("cp.async.commit_group;" ::: "memory");                    \
    } while (0)

    LDGSUM(0);
    GELUSTS(0u);
    LDGSUM(1);
    PREFETCH_B2(0); PREFETCH_B2(1); PREFETCH_B2(2);

#pragma unroll 1
    for (int kt = 0; kt < NKT; kt++) {
        asm volatile("cp.async.wait_group 2;" ::: "memory");
        __syncthreads();   // B(kt) + A stores visible; compute(kt-1) closed

        PREFETCH_B2(kt + 3);   // reuses slot of B(kt-1), readers done

        const uint32_t abB = abase0 + (uint32_t)((kt & 1) * AT2B);
        const uint32_t bbB = bbase + (uint32_t)((kt & 3) * AT2B);
        // 2 k-steps of 16 per 32-K tile (k16 = 32 bytes)
#pragma unroll
        for (int ks2 = 0; ks2 < 2; ks2++) {
            const uint32_t kkB = (uint32_t)(ks2 * 32);
            uint32_t af[4][4], bq[4][2];
            ldsm4(af[0][0], af[0][1], af[0][2], af[0][3], abB + aoff[0] + kkB);
            ldsm4(af[1][0], af[1][1], af[1][2], af[1][3], abB + aoff[1] + kkB);
            ldsm4(af[2][0], af[2][1], af[2][2], af[2][3], abB + aoff[2] + kkB);
            ldsm4(af[3][0], af[3][1], af[3][2], af[3][3], abB + aoff[3] + kkB);
            ldsm4(bq[0][0], bq[0][1], bq[1][0], bq[1][1], bbB + boff0 + kkB);
            ldsm4(bq[2][0], bq[2][1], bq[3][0], bq[3][1], bbB + boff1 + kkB);
#pragma unroll
            for (int s = 0; s < 4; s++)
#pragma unroll
                for (int q = 0; q < 4; q++)
                    mma16(c[s][q], af[s], bq[q]);
        }

        if (kt + 1 < NKT) GELUSTS((uint32_t)(((kt + 1) & 1) * AT2B));
        if (kt + 2 < NKT) LDGSUM(kt + 2);
    }

    // Epilogue: out shape (BATCH, INST, NVOCAB) fp32
#pragma unroll
    for (int s = 0; s < 4; s++) {
        int rowb = mt * 128 + wm + s * 16 + g;
#pragma unroll
        for (int q = 0; q < 4; q++) {
            int col = wn + q * 8 + 2 * tg;
            *reinterpret_cast<float2*>(out + ((size_t)rowb * INST + inst) * NVOCAB + col) =
                make_float2(c[s][q][0], c[s][q][1]);
            *reinterpret_cast<float2*>(out + ((size_t)(rowb + 8) * INST + inst) * NVOCAB + col) =
                make_float2(c[s][q][2], c[s][q][3]);
        }
    }
}

// ---------------------------------------------------------------------------
extern "C" void kernel_launch(void* const* d_in, const int* in_sizes, int n_in,
                              void* d_out, int out_size)
{
    const int*   a  = (const int*)d_in[0];
    const float* El = (const float*)d_in[1];
    const float* Er = (const float*)d_in[2];
    const float* W1 = (const float*)d_in[3];
    const float* W2 = (const float*)d_in[4];
    float* out = (float*)d_out;

    static int configured = 0;
    if (!configured) {
        cudaFuncSetAttribute(phase1_kernel,
                             cudaFuncAttributeMaxDynamicSharedMemorySize, P1_SMEM);
        cudaFuncSetAttribute(phase2_kernel,
                             cudaFuncAttributeMaxDynamicSharedMemorySize, P2_SMEM);
        configured = 1;
    }

    dim3 g1(HID / 128, INST, 2);
    phase1_kernel<<<g1, 256, P1_SMEM>>>(El, Er, W1, W2);

    dim3 g2(BATCH / 128, INST);
    phase2_kernel<<<g2, 256, P2_SMEM>>>(a, out);
}